// round 10
// baseline (speedup 1.0000x reference)
#include <cuda_runtime.h>
#include <cstdint>

// Problem constants
#define N_ 32768
#define D_ 512
#define Q_ 4
#define K_ 2048

// GEMM tiling (int8)
#define BM 128
#define BN 128
#define BKI 64
#define NIT (D_ / BKI)   // 8
#define STAGES 3
#define CMAX 128
#define MARGIN 16.0f

// ---------------- device scratch ----------------
__device__ float g_res[N_ * D_];                    // fp32 residual (64 MB)
__device__ int8_t g_qres[N_ * D_];                  // int8 residual (16 MB)
__device__ int8_t g_qcb[Q_ * K_ * D_];              // int8 codebooks (4 MB)
__device__ float g_rn2[N_];
__device__ float g_sa[N_];
__device__ float g_en2[Q_ * K_];
__device__ float g_sb[Q_ * K_];
__device__ unsigned long long g_key[N_];            // global coarse min (dist_bits<<32)|k
__device__ unsigned long long g_cand[(size_t)N_ * CMAX];
__device__ int g_ccnt[N_];
__device__ int g_done[256];                         // per row-group completion tickets
__device__ double g_lossp[256];

// ---------------- PTX helpers ----------------
__device__ __forceinline__ void cp_async16(uint32_t saddr, const void* gaddr) {
    asm volatile("cp.async.cg.shared.global [%0], [%1], 16;" :: "r"(saddr), "l"(gaddr));
}
#define CP_COMMIT() asm volatile("cp.async.commit_group;")
#define CP_WAIT1()  asm volatile("cp.async.wait_group 1;")

__device__ __forceinline__ void ldsm4(uint32_t& r0, uint32_t& r1, uint32_t& r2, uint32_t& r3,
                                      uint32_t addr) {
    asm volatile("ldmatrix.sync.aligned.m8n8.x4.shared.b16 {%0,%1,%2,%3}, [%4];"
                 : "=r"(r0), "=r"(r1), "=r"(r2), "=r"(r3) : "r"(addr));
}
__device__ __forceinline__ void mma_s8(int* c, const uint32_t* a, const uint32_t* b) {
    asm volatile(
        "mma.sync.aligned.m16n8k32.row.col.s32.s8.s8.s32 "
        "{%0,%1,%2,%3}, {%4,%5,%6,%7}, {%8,%9}, {%0,%1,%2,%3};"
        : "+r"(c[0]), "+r"(c[1]), "+r"(c[2]), "+r"(c[3])
        : "r"(a[0]), "r"(a[1]), "r"(a[2]), "r"(a[3]), "r"(b[0]), "r"(b[1]));
}

__device__ __forceinline__ int8_t q8(float v, float inv) {
    int t = __float2int_rn(v * inv);
    t = max(-127, min(127, t));
    return (int8_t)t;
}

// ---------------- prep (fused init): res = x, rn2, amax, int8 quant ----------------
__global__ void prep_kernel(const float* __restrict__ x) {
    int w = (blockIdx.x * blockDim.x + threadIdx.x) >> 5;
    int lane = threadIdx.x & 31;
    if (w >= N_) return;
    const float4* row = reinterpret_cast<const float4*>(x + (size_t)w * D_);
    float4* rrow = reinterpret_cast<float4*>(g_res + (size_t)w * D_);
    float4 v[4];
    float ss = 0.0f, am = 0.0f;
#pragma unroll
    for (int i = 0; i < 4; i++) {
        v[i] = row[lane + i * 32];
        rrow[lane + i * 32] = v[i];
        ss += v[i].x * v[i].x + v[i].y * v[i].y + v[i].z * v[i].z + v[i].w * v[i].w;
        am = fmaxf(am, fmaxf(fmaxf(fabsf(v[i].x), fabsf(v[i].y)),
                             fmaxf(fabsf(v[i].z), fabsf(v[i].w))));
    }
#pragma unroll
    for (int off = 16; off > 0; off >>= 1) {
        ss += __shfl_xor_sync(0xFFFFFFFFu, ss, off);
        am = fmaxf(am, __shfl_xor_sync(0xFFFFFFFFu, am, off));
    }
    float inv = (am > 0.0f) ? 127.0f / am : 0.0f;
    char4* orow = reinterpret_cast<char4*>(g_qres + (size_t)w * D_);
#pragma unroll
    for (int i = 0; i < 4; i++) {
        char4 c;
        c.x = q8(v[i].x, inv); c.y = q8(v[i].y, inv);
        c.z = q8(v[i].z, inv); c.w = q8(v[i].w, inv);
        orow[lane + i * 32] = c;
    }
    if (lane == 0) { g_rn2[w] = ss; g_sa[w] = am / 127.0f; }
}

// ---------------- codebook: en2 + amax + int8 quant + global resets ----------------
__global__ void cbfuse_kernel(const float* __restrict__ cbs) {
    int gidx = blockIdx.x * blockDim.x + threadIdx.x;
    if (gidx < N_) { g_ccnt[gidx] = 0; g_key[gidx] = ~0ull; }
    if (gidx < 256) { g_lossp[gidx] = 0.0; g_done[gidx] = 0; }
    int w = gidx >> 5;
    int lane = threadIdx.x & 31;
    if (w >= Q_ * K_) return;
    const float4* row = reinterpret_cast<const float4*>(cbs + (size_t)w * D_);
    float4 v[4];
    float ss = 0.0f, am = 0.0f;
#pragma unroll
    for (int i = 0; i < 4; i++) {
        v[i] = row[lane + i * 32];
        ss += v[i].x * v[i].x + v[i].y * v[i].y + v[i].z * v[i].z + v[i].w * v[i].w;
        am = fmaxf(am, fmaxf(fmaxf(fabsf(v[i].x), fabsf(v[i].y)),
                             fmaxf(fabsf(v[i].z), fabsf(v[i].w))));
    }
#pragma unroll
    for (int off = 16; off > 0; off >>= 1) {
        ss += __shfl_xor_sync(0xFFFFFFFFu, ss, off);
        am = fmaxf(am, __shfl_xor_sync(0xFFFFFFFFu, am, off));
    }
    float inv = (am > 0.0f) ? 127.0f / am : 0.0f;
    char4* orow = reinterpret_cast<char4*>(g_qcb + (size_t)w * D_);
#pragma unroll
    for (int i = 0; i < 4; i++) {
        char4 c;
        c.x = q8(v[i].x, inv); c.y = q8(v[i].y, inv);
        c.z = q8(v[i].z, inv); c.w = q8(v[i].w, inv);
        orow[lane + i * 32] = c;
    }
    if (lane == 0) { g_en2[w] = ss; g_sb[w] = am / 127.0f; }
}

// ---------------- int8 coarse GEMM + candidate selection + fused fixup ----------------
// grid (K_/BN = 16 [x, fastest], N_/BM = 256 [y]); the 16 blocks of a row-group are
// launch-adjacent; the last to finish runs the group's fixup (hidden under other
// blocks' tensor work).
__global__ __launch_bounds__(256, 2)
void gemm_dist_kernel(int q, const float* __restrict__ cb, const float* __restrict__ x,
                      float* __restrict__ xq, float* __restrict__ idx_out) {
    // one raw buffer; GEMM layout while computing, fixup layout afterwards
    __shared__ alignas(128) unsigned char Sraw[52224];
    __shared__ int s_ticket;

    int8_t* sAbase = reinterpret_cast<int8_t*>(Sraw);                 // 3 x 8192
    int8_t* sBbase = reinterpret_cast<int8_t*>(Sraw + 24576);        // 3 x 8192
    float* s_en2 = reinterpret_cast<float*>(Sraw + 49152);
    float* s_rn2 = reinterpret_cast<float*>(Sraw + 49664);
    float* s_sa  = reinterpret_cast<float*>(Sraw + 50176);
    float* s_sb  = reinterpret_cast<float*>(Sraw + 50688);
    unsigned long long* rowKey = reinterpret_cast<unsigned long long*>(Sraw + 51200);

    const int tid = threadIdx.x;
    const int wid = tid >> 5;
    const int lane = tid & 31;
    const int warp_m = wid >> 1;
    const int warp_n = wid & 1;
    const int gid = lane >> 2;
    const int tig = lane & 3;

    const int nBase = blockIdx.y * BM;
    const int kBase = blockIdx.x * BN;

    if (tid < 128) {
        s_en2[tid] = g_en2[q * K_ + kBase + tid];
        s_sb[tid]  = g_sb[q * K_ + kBase + tid];
        s_rn2[tid] = g_rn2[nBase + tid];
        s_sa[tid]  = g_sa[nBase + tid];
        rowKey[tid] = ~0ull;
    }

    const int8_t* gA = g_qres;
    const int8_t* gB = g_qcb + (size_t)q * K_ * D_;

    uint32_t saA[STAGES], saB[STAGES];
#pragma unroll
    for (int s = 0; s < STAGES; s++) {
        saA[s] = (uint32_t)__cvta_generic_to_shared(sAbase + s * (BM * BKI));
        saB[s] = (uint32_t)__cvta_generic_to_shared(sBbase + s * (BN * BKI));
    }

    int c[2][8][4];
#pragma unroll
    for (int i = 0; i < 2; i++)
#pragma unroll
        for (int j = 0; j < 8; j++)
#pragma unroll
            for (int v = 0; v < 4; v++) c[i][j][v] = 0;

    auto load_tiles = [&](int s, int it) {
#pragma unroll
        for (int u = 0; u < 2; u++) {
            int cidx = tid + 256 * u;
            int r = cidx >> 2, ch = cidx & 3;
            uint32_t off = (uint32_t)(r * 64 + ((ch ^ (r & 3)) << 4));
            cp_async16(saA[s] + off, gA + (size_t)(nBase + r) * D_ + it * BKI + ch * 16);
            cp_async16(saB[s] + off, gB + (size_t)(kBase + r) * D_ + it * BKI + ch * 16);
        }
    };

    load_tiles(0, 0); CP_COMMIT();
    load_tiles(1, 1); CP_COMMIT();

    for (int it = 0; it < NIT; it++) {
        int buf = it % STAGES;
        CP_WAIT1();
        __syncthreads();
        if (it + 2 < NIT) load_tiles((it + 2) % STAGES, it + 2);
        CP_COMMIT();

#pragma unroll
        for (int kk = 0; kk < 2; kk++) {
            uint32_t a[2][4], b[8][2];
#pragma unroll
            for (int i = 0; i < 2; i++) {
                int row = warp_m * 32 + i * 16 + (lane & 7) + ((lane >> 3) & 1) * 8;
                int ch = kk * 2 + (lane >> 4);
                uint32_t addr = saA[buf] + (uint32_t)(row * 64 + ((ch ^ (row & 3)) << 4));
                ldsm4(a[i][0], a[i][1], a[i][2], a[i][3], addr);
            }
#pragma unroll
            for (int p = 0; p < 4; p++) {
                int row = warp_n * 64 + p * 16 + (lane & 7) + ((lane >> 4) & 1) * 8;
                int ch = kk * 2 + ((lane >> 3) & 1);
                uint32_t addr = saB[buf] + (uint32_t)(row * 64 + ((ch ^ (row & 3)) << 4));
                ldsm4(b[2 * p][0], b[2 * p][1], b[2 * p + 1][0], b[2 * p + 1][1], addr);
            }
#pragma unroll
            for (int i = 0; i < 2; i++)
#pragma unroll
                for (int j = 0; j < 8; j++)
                    mma_s8(c[i][j], a[i], b[j]);
        }
    }

    // ---- epilogue pass 1: dists + block-local row min ----
#pragma unroll
    for (int i = 0; i < 2; i++) {
#pragma unroll
        for (int r2 = 0; r2 < 2; r2++) {
            int rowL = warp_m * 32 + i * 16 + gid + r2 * 8;
            float rn2 = s_rn2[rowL];
            float sc2 = 2.0f * s_sa[rowL];
            unsigned long long best = ~0ull;
#pragma unroll
            for (int j = 0; j < 8; j++) {
                int colL = warp_n * 64 + j * 8 + tig * 2;
                float d0 = rn2 + s_en2[colL] - sc2 * s_sb[colL] * (float)c[i][j][r2 * 2 + 0];
                float d1 = rn2 + s_en2[colL + 1] - sc2 * s_sb[colL + 1] * (float)c[i][j][r2 * 2 + 1];
                c[i][j][r2 * 2 + 0] = __float_as_int(d0);
                c[i][j][r2 * 2 + 1] = __float_as_int(d1);
                unsigned kg0 = (unsigned)(kBase + colL);
                unsigned long long k0 = ((unsigned long long)__float_as_uint(d0) << 32) | kg0;
                unsigned long long k1 = ((unsigned long long)__float_as_uint(d1) << 32) | (kg0 + 1);
                if (k0 < best) best = k0;
                if (k1 < best) best = k1;
            }
#pragma unroll
            for (int m = 1; m < 4; m <<= 1) {
                unsigned long long o = __shfl_xor_sync(0xFFFFFFFFu, best, m);
                if (o < best) best = o;
            }
            if (tig == 0) atomicMin(&rowKey[rowL], best);
        }
    }
    __syncthreads();
    if (tid < 128) {
        unsigned long long mine = rowKey[tid];
        unsigned long long old = atomicMin(&g_key[nBase + tid], mine);
        rowKey[tid] = (old < mine) ? old : mine;
    }
    __syncthreads();

    // ---- epilogue pass 2: append candidates below (best-known min) + MARGIN ----
#pragma unroll
    for (int i = 0; i < 2; i++) {
#pragma unroll
        for (int r2 = 0; r2 < 2; r2++) {
            int rowL = warp_m * 32 + i * 16 + gid + r2 * 8;
            int rowG = nBase + rowL;
            float thr = __uint_as_float((unsigned)(rowKey[rowL] >> 32)) + MARGIN;
#pragma unroll
            for (int j = 0; j < 8; j++) {
                int colL = warp_n * 64 + j * 8 + tig * 2;
#pragma unroll
                for (int v = 0; v < 2; v++) {
                    float d = __int_as_float(c[i][j][r2 * 2 + v]);
                    if (d < thr) {
                        int p = atomicAdd(&g_ccnt[rowG], 1);
                        if (p < CMAX)
                            g_cand[(size_t)rowG * CMAX + p] =
                                ((unsigned long long)__float_as_uint(d) << 32) |
                                (unsigned)(kBase + colL + v);
                    }
                }
            }
        }
    }

    // ---- ticket: last k-block of this row-group performs the fixup ----
    __threadfence();
    __syncthreads();
    if (tid == 0) s_ticket = atomicAdd(&g_done[blockIdx.y], 1);
    __syncthreads();
    if (s_ticket != 15) return;
    __threadfence();
    __syncthreads();   // GEMM smem fully dead; reuse for fixup

    float* fres = reinterpret_cast<float*>(Sraw);            // 8 x 512 floats (16 KB)
    float* fcb  = reinterpret_cast<float*>(Sraw + 16384);    // 8 x 2 x 516 floats (33 KB)

    for (int t = 0; t < 16; t++) {
        int r = nBase + wid + 8 * t;

        const float4* res4 = reinterpret_cast<const float4*>(g_res + (size_t)r * D_);
        float4 rv[4];
#pragma unroll
        for (int i = 0; i < 4; i++) rv[i] = res4[lane + i * 32];

        unsigned long long gk = g_key[r];
        int nc = min(g_ccnt[r], CMAX);
        float thr = __uint_as_float((unsigned)(gk >> 32)) + MARGIN;
        float rn2 = g_rn2[r];

        int kbest;
        if (nc <= 1) {
            // sole in-margin candidate is the coarse min -> provably the exact best
            kbest = (int)(unsigned)(gk & 0xFFFFFFFFull);
        } else {
            float* sr = fres + wid * 512;
#pragma unroll
            for (int i = 0; i < 4; i++)
                reinterpret_cast<float4*>(sr)[lane + i * 32] = rv[i];
            __syncwarp();

            unsigned long long best = ~0ull;
            for (int base = 0; base < nc; base += 2) {
                unsigned long long cd = ~0ull;
                if (lane < 2 && base + lane < nc)
                    cd = g_cand[(size_t)r * CMAX + base + lane];
                float cdist = __uint_as_float((unsigned)(cd >> 32));
                int kc = (int)(unsigned)(cd & 0xFFFFFFFFull);
                bool valid = (lane < 2) && (base + lane < nc) && (cdist < thr);
                unsigned vm = __ballot_sync(0xFFFFFFFFu, valid);

#pragma unroll
                for (int j = 0; j < 2; j++) {
                    if (!((vm >> j) & 1)) continue;
                    int kj = __shfl_sync(0xFFFFFFFFu, kc, j);
                    const float4* crow = reinterpret_cast<const float4*>(cb + (size_t)kj * D_);
                    float4* dst = reinterpret_cast<float4*>(fcb + (wid * 2 + j) * 516);
#pragma unroll
                    for (int i = 0; i < 4; i++) dst[lane + i * 32] = crow[lane + i * 32];
                }
                __syncwarp();

                if (valid) {
                    // exact rescore: ascending-d sequential fmaf chain (matches R1 bits)
                    float dot = 0.0f;
                    const float* sc = fcb + (wid * 2 + lane) * 516;
#pragma unroll 8
                    for (int d = 0; d < D_; d++)
                        dot = fmaf(sr[d], sc[d], dot);
                    float dist = (rn2 + g_en2[q * K_ + kc]) - 2.0f * dot;
                    unsigned long long key =
                        ((unsigned long long)__float_as_uint(dist) << 32) | (unsigned)kc;
                    if (key < best) best = key;
                }
                __syncwarp();
            }
#pragma unroll
            for (int m = 16; m > 0; m >>= 1) {
                unsigned long long o = __shfl_xor_sync(0xFFFFFFFFu, best, m);
                if (o < best) best = o;
            }
            kbest = (int)(unsigned)(best & 0xFFFFFFFFull);
        }

        // residual update + reductions
        const float4* e4 = reinterpret_cast<const float4*>(cb + (size_t)kbest * D_);
        float4 nr[4];
        float ss = 0.0f, am = 0.0f;
#pragma unroll
        for (int i = 0; i < 4; i++) {
            float4 e = e4[lane + i * 32];
            nr[i] = make_float4(rv[i].x - e.x, rv[i].y - e.y, rv[i].z - e.z, rv[i].w - e.w);
            ss += nr[i].x * nr[i].x + nr[i].y * nr[i].y + nr[i].z * nr[i].z + nr[i].w * nr[i].w;
            am = fmaxf(am, fmaxf(fmaxf(fabsf(nr[i].x), fabsf(nr[i].y)),
                                 fmaxf(fabsf(nr[i].z), fabsf(nr[i].w))));
        }
#pragma unroll
        for (int off = 16; off > 0; off >>= 1) {
            ss += __shfl_xor_sync(0xFFFFFFFFu, ss, off);
            am = fmaxf(am, __shfl_xor_sync(0xFFFFFFFFu, am, off));
        }

        if (q < Q_ - 1) {
            float4* orow = reinterpret_cast<float4*>(g_res + (size_t)r * D_);
            float inv = (am > 0.0f) ? 127.0f / am : 0.0f;
            char4* qrow = reinterpret_cast<char4*>(g_qres + (size_t)r * D_);
#pragma unroll
            for (int i = 0; i < 4; i++) {
                orow[lane + i * 32] = nr[i];
                char4 cq;
                cq.x = q8(nr[i].x, inv); cq.y = q8(nr[i].y, inv);
                cq.z = q8(nr[i].z, inv); cq.w = q8(nr[i].w, inv);
                qrow[lane + i * 32] = cq;
            }
            if (lane == 0) {
                g_rn2[r] = ss;
                g_sa[r] = am / 127.0f;
                g_ccnt[r] = 0;
                g_key[r] = ~0ull;
            }
        } else {
            // last stage: emit xq = x - residual_final directly
            const float4* x4 = reinterpret_cast<const float4*>(x + (size_t)r * D_);
            float4* o4 = reinterpret_cast<float4*>(xq + (size_t)r * D_);
#pragma unroll
            for (int i = 0; i < 4; i++) {
                float4 xv = x4[lane + i * 32];
                o4[lane + i * 32] = make_float4(xv.x - nr[i].x, xv.y - nr[i].y,
                                                xv.z - nr[i].z, xv.w - nr[i].w);
            }
        }
        if (lane == 0) {
            idx_out[(size_t)r * Q_ + q] = (float)kbest;
            atomicAdd(&g_lossp[(q << 6) | (r & 63)], (double)ss);
        }
    }
    if (tid == 0) g_done[blockIdx.y] = 0;   // reset ticket for the next stage
}

// ---------------- finalize mean loss ----------------
__global__ void finalize_kernel(float* __restrict__ loss_out) {
    if (threadIdx.x == 0) {
        double s = 0.0;
        for (int i = 0; i < 256; i++) s += g_lossp[i];
        double ml = (s * 1.25 / ((double)N_ * (double)D_)) / (double)Q_;
        *loss_out = (float)ml;
    }
}

// ---------------- launch ----------------
extern "C" void kernel_launch(void* const* d_in, const int* in_sizes, int n_in,
                              void* d_out, int out_size) {
    const float* x = (const float*)d_in[0];
    const float* cbs = (const float*)d_in[1];
    float* out = (float*)d_out;
    float* xq = out;                                  // [N, D]
    float* loss_out = out + (size_t)N_ * D_;          // scalar
    float* idx_out = out + (size_t)N_ * D_ + 1;       // [N, Q] as float

    prep_kernel<<<N_ / 8, 256>>>(x);
    cbfuse_kernel<<<(Q_ * K_) / 8, 256>>>(cbs);

    for (int q = 0; q < Q_; q++) {
        const float* cb = cbs + (size_t)q * K_ * D_;
        dim3 grid(K_ / BN, N_ / BM);   // k fastest -> row-group blocks adjacent
        gemm_dist_kernel<<<grid, 256>>>(q, cb, x, xq, idx_out);
    }
    finalize_kernel<<<1, 32>>>(loss_out);
}

// round 11
// speedup vs baseline: 1.3559x; 1.3559x over previous
#include <cuda_runtime.h>
#include <cstdint>

// Problem constants
#define N_ 32768
#define D_ 512
#define Q_ 4
#define K_ 2048

// GEMM tiling (int8)
#define BM 128
#define BN 128
#define BKI 64
#define NIT (D_ / BKI)   // 8
#define STAGES 3
#define CMAX 128
#define MARGIN 16.0f
#define TIE 0.125f

// ---------------- device scratch ----------------
__device__ float g_res[N_ * D_];                    // fp32 residual (64 MB)
__device__ int8_t g_qres[N_ * D_];                  // int8 residual (16 MB)
__device__ int8_t g_qcb[Q_ * K_ * D_];              // int8 codebooks (4 MB)
__device__ float g_rn2[N_];
__device__ float g_sa[N_];
__device__ float g_en2[Q_ * K_];
__device__ float g_sb[Q_ * K_];
__device__ unsigned long long g_key[N_];            // global coarse min (dist_bits<<32)|k
__device__ unsigned long long g_cand[(size_t)N_ * CMAX];
__device__ int g_ccnt[N_];
__device__ double g_lossp[256];

// ---------------- PTX helpers ----------------
__device__ __forceinline__ void cp_async16(uint32_t saddr, const void* gaddr) {
    asm volatile("cp.async.cg.shared.global [%0], [%1], 16;" :: "r"(saddr), "l"(gaddr));
}
#define CP_COMMIT() asm volatile("cp.async.commit_group;")
#define CP_WAIT1()  asm volatile("cp.async.wait_group 1;")

__device__ __forceinline__ void ldsm4(uint32_t& r0, uint32_t& r1, uint32_t& r2, uint32_t& r3,
                                      uint32_t addr) {
    asm volatile("ldmatrix.sync.aligned.m8n8.x4.shared.b16 {%0,%1,%2,%3}, [%4];"
                 : "=r"(r0), "=r"(r1), "=r"(r2), "=r"(r3) : "r"(addr));
}
__device__ __forceinline__ void mma_s8(int* c, const uint32_t* a, const uint32_t* b) {
    asm volatile(
        "mma.sync.aligned.m16n8k32.row.col.s32.s8.s8.s32 "
        "{%0,%1,%2,%3}, {%4,%5,%6,%7}, {%8,%9}, {%0,%1,%2,%3};"
        : "+r"(c[0]), "+r"(c[1]), "+r"(c[2]), "+r"(c[3])
        : "r"(a[0]), "r"(a[1]), "r"(a[2]), "r"(a[3]), "r"(b[0]), "r"(b[1]));
}

__device__ __forceinline__ int8_t q8(float v, float inv) {
    int t = __float2int_rn(v * inv);
    t = max(-127, min(127, t));
    return (int8_t)t;
}

// ---------------- prep (fused init): res = x, rn2, amax, int8 quant ----------------
__global__ void prep_kernel(const float* __restrict__ x) {
    int w = (blockIdx.x * blockDim.x + threadIdx.x) >> 5;
    int lane = threadIdx.x & 31;
    if (w >= N_) return;
    const float4* row = reinterpret_cast<const float4*>(x + (size_t)w * D_);
    float4* rrow = reinterpret_cast<float4*>(g_res + (size_t)w * D_);
    float4 v[4];
    float ss = 0.0f, am = 0.0f;
#pragma unroll
    for (int i = 0; i < 4; i++) {
        v[i] = row[lane + i * 32];
        rrow[lane + i * 32] = v[i];
        ss += v[i].x * v[i].x + v[i].y * v[i].y + v[i].z * v[i].z + v[i].w * v[i].w;
        am = fmaxf(am, fmaxf(fmaxf(fabsf(v[i].x), fabsf(v[i].y)),
                             fmaxf(fabsf(v[i].z), fabsf(v[i].w))));
    }
#pragma unroll
    for (int off = 16; off > 0; off >>= 1) {
        ss += __shfl_xor_sync(0xFFFFFFFFu, ss, off);
        am = fmaxf(am, __shfl_xor_sync(0xFFFFFFFFu, am, off));
    }
    float inv = (am > 0.0f) ? 127.0f / am : 0.0f;
    char4* orow = reinterpret_cast<char4*>(g_qres + (size_t)w * D_);
#pragma unroll
    for (int i = 0; i < 4; i++) {
        char4 c;
        c.x = q8(v[i].x, inv); c.y = q8(v[i].y, inv);
        c.z = q8(v[i].z, inv); c.w = q8(v[i].w, inv);
        orow[lane + i * 32] = c;
    }
    if (lane == 0) { g_rn2[w] = ss; g_sa[w] = am / 127.0f; }
}

// ---------------- codebook: en2 + amax + int8 quant + global resets ----------------
__global__ void cbfuse_kernel(const float* __restrict__ cbs) {
    int gidx = blockIdx.x * blockDim.x + threadIdx.x;
    if (gidx < N_) { g_ccnt[gidx] = 0; g_key[gidx] = ~0ull; }
    if (gidx < 256) g_lossp[gidx] = 0.0;
    int w = gidx >> 5;
    int lane = threadIdx.x & 31;
    if (w >= Q_ * K_) return;
    const float4* row = reinterpret_cast<const float4*>(cbs + (size_t)w * D_);
    float4 v[4];
    float ss = 0.0f, am = 0.0f;
#pragma unroll
    for (int i = 0; i < 4; i++) {
        v[i] = row[lane + i * 32];
        ss += v[i].x * v[i].x + v[i].y * v[i].y + v[i].z * v[i].z + v[i].w * v[i].w;
        am = fmaxf(am, fmaxf(fmaxf(fabsf(v[i].x), fabsf(v[i].y)),
                             fmaxf(fabsf(v[i].z), fabsf(v[i].w))));
    }
#pragma unroll
    for (int off = 16; off > 0; off >>= 1) {
        ss += __shfl_xor_sync(0xFFFFFFFFu, ss, off);
        am = fmaxf(am, __shfl_xor_sync(0xFFFFFFFFu, am, off));
    }
    float inv = (am > 0.0f) ? 127.0f / am : 0.0f;
    char4* orow = reinterpret_cast<char4*>(g_qcb + (size_t)w * D_);
#pragma unroll
    for (int i = 0; i < 4; i++) {
        char4 c;
        c.x = q8(v[i].x, inv); c.y = q8(v[i].y, inv);
        c.z = q8(v[i].z, inv); c.w = q8(v[i].w, inv);
        orow[lane + i * 32] = c;
    }
    if (lane == 0) { g_en2[w] = ss; g_sb[w] = am / 127.0f; }
}

// ---------------- int8 coarse GEMM + candidate selection ----------------
__global__ __launch_bounds__(256, 2)
void gemm_dist_kernel(int q) {
    __shared__ alignas(128) int8_t sA[STAGES][BM * BKI];
    __shared__ alignas(128) int8_t sB[STAGES][BN * BKI];
    __shared__ float s_en2[BN];
    __shared__ float s_rn2[BM];
    __shared__ float s_sa[BM];
    __shared__ float s_sb[BN];
    __shared__ unsigned long long rowKey[BM];

    const int tid = threadIdx.x;
    const int wid = tid >> 5;
    const int lane = tid & 31;
    const int warp_m = wid >> 1;
    const int warp_n = wid & 1;
    const int gid = lane >> 2;
    const int tig = lane & 3;

    const int nBase = blockIdx.x * BM;
    const int kBase = blockIdx.y * BN;

    if (tid < 128) {
        s_en2[tid] = g_en2[q * K_ + kBase + tid];
        s_sb[tid]  = g_sb[q * K_ + kBase + tid];
        s_rn2[tid] = g_rn2[nBase + tid];
        s_sa[tid]  = g_sa[nBase + tid];
        rowKey[tid] = ~0ull;
    }

    const int8_t* gA = g_qres;
    const int8_t* gB = g_qcb + (size_t)q * K_ * D_;

    uint32_t saA[STAGES], saB[STAGES];
#pragma unroll
    for (int s = 0; s < STAGES; s++) {
        saA[s] = (uint32_t)__cvta_generic_to_shared(&sA[s][0]);
        saB[s] = (uint32_t)__cvta_generic_to_shared(&sB[s][0]);
    }

    int c[2][8][4];
#pragma unroll
    for (int i = 0; i < 2; i++)
#pragma unroll
        for (int j = 0; j < 8; j++)
#pragma unroll
            for (int v = 0; v < 4; v++) c[i][j][v] = 0;

    auto load_tiles = [&](int s, int it) {
#pragma unroll
        for (int u = 0; u < 2; u++) {
            int cidx = tid + 256 * u;
            int r = cidx >> 2, ch = cidx & 3;
            uint32_t off = (uint32_t)(r * 64 + ((ch ^ (r & 3)) << 4));
            cp_async16(saA[s] + off, gA + (size_t)(nBase + r) * D_ + it * BKI + ch * 16);
            cp_async16(saB[s] + off, gB + (size_t)(kBase + r) * D_ + it * BKI + ch * 16);
        }
    };

    load_tiles(0, 0); CP_COMMIT();
    load_tiles(1, 1); CP_COMMIT();

    for (int it = 0; it < NIT; it++) {
        int buf = it % STAGES;
        CP_WAIT1();
        __syncthreads();
        if (it + 2 < NIT) load_tiles((it + 2) % STAGES, it + 2);
        CP_COMMIT();

#pragma unroll
        for (int kk = 0; kk < 2; kk++) {
            uint32_t a[2][4], b[8][2];
#pragma unroll
            for (int i = 0; i < 2; i++) {
                int row = warp_m * 32 + i * 16 + (lane & 7) + ((lane >> 3) & 1) * 8;
                int ch = kk * 2 + (lane >> 4);
                uint32_t addr = saA[buf] + (uint32_t)(row * 64 + ((ch ^ (row & 3)) << 4));
                ldsm4(a[i][0], a[i][1], a[i][2], a[i][3], addr);
            }
#pragma unroll
            for (int p = 0; p < 4; p++) {
                int row = warp_n * 64 + p * 16 + (lane & 7) + ((lane >> 4) & 1) * 8;
                int ch = kk * 2 + ((lane >> 3) & 1);
                uint32_t addr = saB[buf] + (uint32_t)(row * 64 + ((ch ^ (row & 3)) << 4));
                ldsm4(b[2 * p][0], b[2 * p][1], b[2 * p + 1][0], b[2 * p + 1][1], addr);
            }
#pragma unroll
            for (int i = 0; i < 2; i++)
#pragma unroll
                for (int j = 0; j < 8; j++)
                    mma_s8(c[i][j], a[i], b[j]);
        }
    }

    // ---- epilogue pass 1: dists + block-local row min ----
#pragma unroll
    for (int i = 0; i < 2; i++) {
#pragma unroll
        for (int r2 = 0; r2 < 2; r2++) {
            int rowL = warp_m * 32 + i * 16 + gid + r2 * 8;
            float rn2 = s_rn2[rowL];
            float sc2 = 2.0f * s_sa[rowL];
            unsigned long long best = ~0ull;
#pragma unroll
            for (int j = 0; j < 8; j++) {
                int colL = warp_n * 64 + j * 8 + tig * 2;
                float d0 = rn2 + s_en2[colL] - sc2 * s_sb[colL] * (float)c[i][j][r2 * 2 + 0];
                float d1 = rn2 + s_en2[colL + 1] - sc2 * s_sb[colL + 1] * (float)c[i][j][r2 * 2 + 1];
                c[i][j][r2 * 2 + 0] = __float_as_int(d0);
                c[i][j][r2 * 2 + 1] = __float_as_int(d1);
                unsigned kg0 = (unsigned)(kBase + colL);
                unsigned long long k0 = ((unsigned long long)__float_as_uint(d0) << 32) | kg0;
                unsigned long long k1 = ((unsigned long long)__float_as_uint(d1) << 32) | (kg0 + 1);
                if (k0 < best) best = k0;
                if (k1 < best) best = k1;
            }
#pragma unroll
            for (int m = 1; m < 4; m <<= 1) {
                unsigned long long o = __shfl_xor_sync(0xFFFFFFFFu, best, m);
                if (o < best) best = o;
            }
            if (tig == 0) atomicMin(&rowKey[rowL], best);
        }
    }
    __syncthreads();
    // global coarse min; tighten local threshold with running global knowledge
    if (tid < 128) {
        unsigned long long mine = rowKey[tid];
        unsigned long long old = atomicMin(&g_key[nBase + tid], mine);
        rowKey[tid] = (old < mine) ? old : mine;
    }
    __syncthreads();

    // ---- epilogue pass 2: append candidates below (best-known min) + MARGIN ----
#pragma unroll
    for (int i = 0; i < 2; i++) {
#pragma unroll
        for (int r2 = 0; r2 < 2; r2++) {
            int rowL = warp_m * 32 + i * 16 + gid + r2 * 8;
            int rowG = nBase + rowL;
            float thr = __uint_as_float((unsigned)(rowKey[rowL] >> 32)) + MARGIN;
#pragma unroll
            for (int j = 0; j < 8; j++) {
                int colL = warp_n * 64 + j * 8 + tig * 2;
#pragma unroll
                for (int v = 0; v < 2; v++) {
                    float d = __int_as_float(c[i][j][r2 * 2 + v]);
                    if (d < thr) {
                        int p = atomicAdd(&g_ccnt[rowG], 1);
                        if (p < CMAX)
                            g_cand[(size_t)rowG * CMAX + p] =
                                ((unsigned long long)__float_as_uint(d) << 32) |
                                (unsigned)(kBase + colL + v);
                    }
                }
            }
        }
    }
}

// ---------------- fixup + full row update, warp-per-row ----------------
// 8 warps/block; approx warp-parallel fp32 rescore; exact chain only for ties.
__global__ __launch_bounds__(256)
void fixup_update_kernel(const float* __restrict__ cb, const float* __restrict__ x,
                         float* __restrict__ xq, float* __restrict__ idx_out, int q) {
    __shared__ float s_dist[8][CMAX];
    __shared__ alignas(16) float sres[8][D_];

    const int tid = threadIdx.x;
    const int wid = tid >> 5;
    const int lane = tid & 31;
    const int r = blockIdx.x * 8 + wid;

    const float4* res4 = reinterpret_cast<const float4*>(g_res + (size_t)r * D_);
    float4 rv[4];
#pragma unroll
    for (int i = 0; i < 4; i++) rv[i] = res4[lane + i * 32];

    unsigned long long gk = g_key[r];
    int nc = min(g_ccnt[r], CMAX);
    float thr = __uint_as_float((unsigned)(gk >> 32)) + MARGIN;
    float rn2 = g_rn2[r];

    int kbest;
    if (nc <= 1) {
        // sole in-margin candidate is the coarse min -> provably the exact best
        kbest = (int)(unsigned)(gk & 0xFFFFFFFFull);
    } else {
        // pass A: warp-parallel fp32 approx distance per candidate
        float bestd = 3.4e38f;
        for (int ci = 0; ci < nc; ci++) {
            unsigned long long cd = g_cand[(size_t)r * CMAX + ci];   // broadcast load
            float cdist = __uint_as_float((unsigned)(cd >> 32));
            if (cdist >= thr) { if (lane == 0) s_dist[wid][ci] = 3.4e38f; continue; }
            int k = (int)(unsigned)(cd & 0xFFFFFFFFull);
            const float4* crow = reinterpret_cast<const float4*>(cb + (size_t)k * D_);
            float dot = 0.0f;
#pragma unroll
            for (int i = 0; i < 4; i++) {
                float4 e = crow[lane + i * 32];
                dot += rv[i].x * e.x + rv[i].y * e.y + rv[i].z * e.z + rv[i].w * e.w;
            }
#pragma unroll
            for (int off = 16; off > 0; off >>= 1)
                dot += __shfl_xor_sync(0xFFFFFFFFu, dot, off);
            float da = rn2 + __ldg(&g_en2[q * K_ + k]) - 2.0f * dot;
            if (lane == 0) s_dist[wid][ci] = da;
            if (da < bestd) bestd = da;    // identical across lanes post-reduce
        }
        __syncwarp();
        // pass B: tie set = candidates within TIE of approx best
        int tcnt = 0, tfirst = -1;
        for (int ci = lane; ci < nc; ci += 32) {
            if (s_dist[wid][ci] < bestd + TIE) { tcnt++; tfirst = ci; }
        }
#pragma unroll
        for (int off = 16; off > 0; off >>= 1) {
            tcnt += __shfl_xor_sync(0xFFFFFFFFu, tcnt, off);
            int o = __shfl_xor_sync(0xFFFFFFFFu, tfirst, off);
            if (o >= 0 && (tfirst < 0)) tfirst = o;
        }
        if (tcnt == 1) {
            // unique: approx ordering == exact ordering (gap > TIE >= 2*eps)
            unsigned long long cd = g_cand[(size_t)r * CMAX + tfirst];
            kbest = (int)(unsigned)(cd & 0xFFFFFFFFull);
        } else {
            // rare: run the exact ascending-d sequential fmaf chain (R1 bits) per tie
#pragma unroll
            for (int i = 0; i < 4; i++)
                reinterpret_cast<float4*>(sres[wid])[lane + i * 32] = rv[i];
            __syncwarp();
            unsigned long long best = ~0ull;
            for (int ci = 0; ci < nc; ci++) {
                if (s_dist[wid][ci] >= bestd + TIE) continue;
                unsigned long long cd = g_cand[(size_t)r * CMAX + ci];
                int k = (int)(unsigned)(cd & 0xFFFFFFFFull);
                if (lane == 0) {
                    const float* crow = cb + (size_t)k * D_;
                    float dot = 0.0f;
#pragma unroll 8
                    for (int d = 0; d < D_; d++)
                        dot = fmaf(sres[wid][d], __ldg(crow + d), dot);
                    float dist = (rn2 + g_en2[q * K_ + k]) - 2.0f * dot;
                    unsigned long long key =
                        ((unsigned long long)__float_as_uint(dist) << 32) | (unsigned)k;
                    if (key < best) best = key;
                }
            }
            best = __shfl_sync(0xFFFFFFFFu, best, 0);
            kbest = (int)(unsigned)(best & 0xFFFFFFFFull);
        }
    }

    // residual update + reductions
    const float4* e4 = reinterpret_cast<const float4*>(cb + (size_t)kbest * D_);
    float4 nr[4];
    float ss = 0.0f, am = 0.0f;
#pragma unroll
    for (int i = 0; i < 4; i++) {
        float4 e = e4[lane + i * 32];
        nr[i] = make_float4(rv[i].x - e.x, rv[i].y - e.y, rv[i].z - e.z, rv[i].w - e.w);
        ss += nr[i].x * nr[i].x + nr[i].y * nr[i].y + nr[i].z * nr[i].z + nr[i].w * nr[i].w;
        am = fmaxf(am, fmaxf(fmaxf(fabsf(nr[i].x), fabsf(nr[i].y)),
                             fmaxf(fabsf(nr[i].z), fabsf(nr[i].w))));
    }
#pragma unroll
    for (int off = 16; off > 0; off >>= 1) {
        ss += __shfl_xor_sync(0xFFFFFFFFu, ss, off);
        am = fmaxf(am, __shfl_xor_sync(0xFFFFFFFFu, am, off));
    }

    if (q < Q_ - 1) {
        float4* orow = reinterpret_cast<float4*>(g_res + (size_t)r * D_);
        float inv = (am > 0.0f) ? 127.0f / am : 0.0f;
        char4* qrow = reinterpret_cast<char4*>(g_qres + (size_t)r * D_);
#pragma unroll
        for (int i = 0; i < 4; i++) {
            orow[lane + i * 32] = nr[i];
            char4 c;
            c.x = q8(nr[i].x, inv); c.y = q8(nr[i].y, inv);
            c.z = q8(nr[i].z, inv); c.w = q8(nr[i].w, inv);
            qrow[lane + i * 32] = c;
        }
        if (lane == 0) {
            g_rn2[r] = ss;
            g_sa[r] = am / 127.0f;
            g_ccnt[r] = 0;
            g_key[r] = ~0ull;
        }
    } else {
        // last stage: emit xq = x - residual_final directly
        const float4* x4 = reinterpret_cast<const float4*>(x + (size_t)r * D_);
        float4* o4 = reinterpret_cast<float4*>(xq + (size_t)r * D_);
#pragma unroll
        for (int i = 0; i < 4; i++) {
            float4 xv = x4[lane + i * 32];
            o4[lane + i * 32] = make_float4(xv.x - nr[i].x, xv.y - nr[i].y,
                                            xv.z - nr[i].z, xv.w - nr[i].w);
        }
    }
    if (lane == 0) {
        idx_out[(size_t)r * Q_ + q] = (float)kbest;
        atomicAdd(&g_lossp[(q << 6) | (r & 63)], (double)ss);
    }
}

// ---------------- finalize mean loss ----------------
__global__ void finalize_kernel(float* __restrict__ loss_out) {
    if (threadIdx.x == 0) {
        double s = 0.0;
        for (int i = 0; i < 256; i++) s += g_lossp[i];
        double ml = (s * 1.25 / ((double)N_ * (double)D_)) / (double)Q_;
        *loss_out = (float)ml;
    }
}

// ---------------- launch ----------------
extern "C" void kernel_launch(void* const* d_in, const int* in_sizes, int n_in,
                              void* d_out, int out_size) {
    const float* x = (const float*)d_in[0];
    const float* cbs = (const float*)d_in[1];
    float* out = (float*)d_out;
    float* xq = out;                                  // [N, D]
    float* loss_out = out + (size_t)N_ * D_;          // scalar
    float* idx_out = out + (size_t)N_ * D_ + 1;       // [N, Q] as float

    prep_kernel<<<N_ / 8, 256>>>(x);
    cbfuse_kernel<<<(Q_ * K_) / 8, 256>>>(cbs);

    for (int q = 0; q < Q_; q++) {
        const float* cb = cbs + (size_t)q * K_ * D_;
        dim3 grid(N_ / BM, K_ / BN);
        gemm_dist_kernel<<<grid, 256>>>(q);
        fixup_update_kernel<<<N_ / 8, 256>>>(cb, x, xq, idx_out, q);
    }
    finalize_kernel<<<1, 32>>>(loss_out);
}

// round 12
// speedup vs baseline: 1.4200x; 1.0472x over previous
#include <cuda_runtime.h>
#include <cstdint>

// Problem constants
#define N_ 32768
#define D_ 512
#define Q_ 4
#define K_ 2048
#define NHALF (N_ / 2)

// GEMM tiling (int8)
#define BM 128
#define BN 128
#define BKI 64
#define NIT (D_ / BKI)   // 8
#define STAGES 3
#define CMAX 128
#define MARGIN 16.0f
#define TIE 0.125f

// ---------------- device scratch ----------------
__device__ float g_res[N_ * D_];                    // fp32 residual (64 MB)
__device__ int8_t g_qres[N_ * D_];                  // int8 residual (16 MB)
__device__ int8_t g_qcb[Q_ * K_ * D_];              // int8 codebooks (4 MB)
__device__ float g_rn2[N_];
__device__ float g_sa[N_];
__device__ float g_en2[Q_ * K_];
__device__ float g_sb[Q_ * K_];
__device__ unsigned long long g_key[N_];            // global coarse min (dist_bits<<32)|k
__device__ unsigned long long g_cand[(size_t)N_ * CMAX];
__device__ int g_ccnt[N_];
__device__ double g_lossp[256];

// ---------------- PTX helpers ----------------
__device__ __forceinline__ void cp_async16(uint32_t saddr, const void* gaddr) {
    asm volatile("cp.async.cg.shared.global [%0], [%1], 16;" :: "r"(saddr), "l"(gaddr));
}
#define CP_COMMIT() asm volatile("cp.async.commit_group;")
#define CP_WAIT1()  asm volatile("cp.async.wait_group 1;")

__device__ __forceinline__ void ldsm4(uint32_t& r0, uint32_t& r1, uint32_t& r2, uint32_t& r3,
                                      uint32_t addr) {
    asm volatile("ldmatrix.sync.aligned.m8n8.x4.shared.b16 {%0,%1,%2,%3}, [%4];"
                 : "=r"(r0), "=r"(r1), "=r"(r2), "=r"(r3) : "r"(addr));
}
__device__ __forceinline__ void mma_s8(int* c, const uint32_t* a, const uint32_t* b) {
    asm volatile(
        "mma.sync.aligned.m16n8k32.row.col.s32.s8.s8.s32 "
        "{%0,%1,%2,%3}, {%4,%5,%6,%7}, {%8,%9}, {%0,%1,%2,%3};"
        : "+r"(c[0]), "+r"(c[1]), "+r"(c[2]), "+r"(c[3])
        : "r"(a[0]), "r"(a[1]), "r"(a[2]), "r"(a[3]), "r"(b[0]), "r"(b[1]));
}

__device__ __forceinline__ int8_t q8(float v, float inv) {
    int t = __float2int_rn(v * inv);
    t = max(-127, min(127, t));
    return (int8_t)t;
}

// ---------------- prep (fused init): res = x, rn2, amax, int8 quant ----------------
__global__ void prep_kernel(const float* __restrict__ x) {
    int w = (blockIdx.x * blockDim.x + threadIdx.x) >> 5;
    int lane = threadIdx.x & 31;
    if (w >= N_) return;
    const float4* row = reinterpret_cast<const float4*>(x + (size_t)w * D_);
    float4* rrow = reinterpret_cast<float4*>(g_res + (size_t)w * D_);
    float4 v[4];
    float ss = 0.0f, am = 0.0f;
#pragma unroll
    for (int i = 0; i < 4; i++) {
        v[i] = row[lane + i * 32];
        rrow[lane + i * 32] = v[i];
        ss += v[i].x * v[i].x + v[i].y * v[i].y + v[i].z * v[i].z + v[i].w * v[i].w;
        am = fmaxf(am, fmaxf(fmaxf(fabsf(v[i].x), fabsf(v[i].y)),
                             fmaxf(fabsf(v[i].z), fabsf(v[i].w))));
    }
#pragma unroll
    for (int off = 16; off > 0; off >>= 1) {
        ss += __shfl_xor_sync(0xFFFFFFFFu, ss, off);
        am = fmaxf(am, __shfl_xor_sync(0xFFFFFFFFu, am, off));
    }
    float inv = (am > 0.0f) ? 127.0f / am : 0.0f;
    char4* orow = reinterpret_cast<char4*>(g_qres + (size_t)w * D_);
#pragma unroll
    for (int i = 0; i < 4; i++) {
        char4 c;
        c.x = q8(v[i].x, inv); c.y = q8(v[i].y, inv);
        c.z = q8(v[i].z, inv); c.w = q8(v[i].w, inv);
        orow[lane + i * 32] = c;
    }
    if (lane == 0) { g_rn2[w] = ss; g_sa[w] = am / 127.0f; }
}

// ---------------- codebook: en2 + amax + int8 quant + global resets ----------------
__global__ void cbfuse_kernel(const float* __restrict__ cbs) {
    int gidx = blockIdx.x * blockDim.x + threadIdx.x;
    if (gidx < N_) { g_ccnt[gidx] = 0; g_key[gidx] = ~0ull; }
    if (gidx < 256) g_lossp[gidx] = 0.0;
    int w = gidx >> 5;
    int lane = threadIdx.x & 31;
    if (w >= Q_ * K_) return;
    const float4* row = reinterpret_cast<const float4*>(cbs + (size_t)w * D_);
    float4 v[4];
    float ss = 0.0f, am = 0.0f;
#pragma unroll
    for (int i = 0; i < 4; i++) {
        v[i] = row[lane + i * 32];
        ss += v[i].x * v[i].x + v[i].y * v[i].y + v[i].z * v[i].z + v[i].w * v[i].w;
        am = fmaxf(am, fmaxf(fmaxf(fabsf(v[i].x), fabsf(v[i].y)),
                             fmaxf(fabsf(v[i].z), fabsf(v[i].w))));
    }
#pragma unroll
    for (int off = 16; off > 0; off >>= 1) {
        ss += __shfl_xor_sync(0xFFFFFFFFu, ss, off);
        am = fmaxf(am, __shfl_xor_sync(0xFFFFFFFFu, am, off));
    }
    float inv = (am > 0.0f) ? 127.0f / am : 0.0f;
    char4* orow = reinterpret_cast<char4*>(g_qcb + (size_t)w * D_);
#pragma unroll
    for (int i = 0; i < 4; i++) {
        char4 c;
        c.x = q8(v[i].x, inv); c.y = q8(v[i].y, inv);
        c.z = q8(v[i].z, inv); c.w = q8(v[i].w, inv);
        orow[lane + i * 32] = c;
    }
    if (lane == 0) { g_en2[w] = ss; g_sb[w] = am / 127.0f; }
}

// ---------------- int8 coarse GEMM + candidate selection (row half) ----------------
__global__ __launch_bounds__(256, 2)
void gemm_dist_kernel(int q, int rBase) {
    __shared__ alignas(128) int8_t sA[STAGES][BM * BKI];
    __shared__ alignas(128) int8_t sB[STAGES][BN * BKI];
    __shared__ float s_en2[BN];
    __shared__ float s_rn2[BM];
    __shared__ float s_sa[BM];
    __shared__ float s_sb[BN];
    __shared__ unsigned long long rowKey[BM];

    const int tid = threadIdx.x;
    const int wid = tid >> 5;
    const int lane = tid & 31;
    const int warp_m = wid >> 1;
    const int warp_n = wid & 1;
    const int gid = lane >> 2;
    const int tig = lane & 3;

    const int nBase = rBase + blockIdx.x * BM;
    const int kBase = blockIdx.y * BN;

    if (tid < 128) {
        s_en2[tid] = g_en2[q * K_ + kBase + tid];
        s_sb[tid]  = g_sb[q * K_ + kBase + tid];
        s_rn2[tid] = g_rn2[nBase + tid];
        s_sa[tid]  = g_sa[nBase + tid];
        rowKey[tid] = ~0ull;
    }

    const int8_t* gA = g_qres;
    const int8_t* gB = g_qcb + (size_t)q * K_ * D_;

    uint32_t saA[STAGES], saB[STAGES];
#pragma unroll
    for (int s = 0; s < STAGES; s++) {
        saA[s] = (uint32_t)__cvta_generic_to_shared(&sA[s][0]);
        saB[s] = (uint32_t)__cvta_generic_to_shared(&sB[s][0]);
    }

    int c[2][8][4];
#pragma unroll
    for (int i = 0; i < 2; i++)
#pragma unroll
        for (int j = 0; j < 8; j++)
#pragma unroll
            for (int v = 0; v < 4; v++) c[i][j][v] = 0;

    auto load_tiles = [&](int s, int it) {
#pragma unroll
        for (int u = 0; u < 2; u++) {
            int cidx = tid + 256 * u;
            int r = cidx >> 2, ch = cidx & 3;
            uint32_t off = (uint32_t)(r * 64 + ((ch ^ (r & 3)) << 4));
            cp_async16(saA[s] + off, gA + (size_t)(nBase + r) * D_ + it * BKI + ch * 16);
            cp_async16(saB[s] + off, gB + (size_t)(kBase + r) * D_ + it * BKI + ch * 16);
        }
    };

    load_tiles(0, 0); CP_COMMIT();
    load_tiles(1, 1); CP_COMMIT();

    for (int it = 0; it < NIT; it++) {
        int buf = it % STAGES;
        CP_WAIT1();
        __syncthreads();
        if (it + 2 < NIT) load_tiles((it + 2) % STAGES, it + 2);
        CP_COMMIT();

#pragma unroll
        for (int kk = 0; kk < 2; kk++) {
            uint32_t a[2][4], b[8][2];
#pragma unroll
            for (int i = 0; i < 2; i++) {
                int row = warp_m * 32 + i * 16 + (lane & 7) + ((lane >> 3) & 1) * 8;
                int ch = kk * 2 + (lane >> 4);
                uint32_t addr = saA[buf] + (uint32_t)(row * 64 + ((ch ^ (row & 3)) << 4));
                ldsm4(a[i][0], a[i][1], a[i][2], a[i][3], addr);
            }
#pragma unroll
            for (int p = 0; p < 4; p++) {
                int row = warp_n * 64 + p * 16 + (lane & 7) + ((lane >> 4) & 1) * 8;
                int ch = kk * 2 + ((lane >> 3) & 1);
                uint32_t addr = saB[buf] + (uint32_t)(row * 64 + ((ch ^ (row & 3)) << 4));
                ldsm4(b[2 * p][0], b[2 * p][1], b[2 * p + 1][0], b[2 * p + 1][1], addr);
            }
#pragma unroll
            for (int i = 0; i < 2; i++)
#pragma unroll
                for (int j = 0; j < 8; j++)
                    mma_s8(c[i][j], a[i], b[j]);
        }
    }

    // ---- epilogue pass 1: dists + block-local row min ----
#pragma unroll
    for (int i = 0; i < 2; i++) {
#pragma unroll
        for (int r2 = 0; r2 < 2; r2++) {
            int rowL = warp_m * 32 + i * 16 + gid + r2 * 8;
            float rn2 = s_rn2[rowL];
            float sc2 = 2.0f * s_sa[rowL];
            unsigned long long best = ~0ull;
#pragma unroll
            for (int j = 0; j < 8; j++) {
                int colL = warp_n * 64 + j * 8 + tig * 2;
                float d0 = rn2 + s_en2[colL] - sc2 * s_sb[colL] * (float)c[i][j][r2 * 2 + 0];
                float d1 = rn2 + s_en2[colL + 1] - sc2 * s_sb[colL + 1] * (float)c[i][j][r2 * 2 + 1];
                c[i][j][r2 * 2 + 0] = __float_as_int(d0);
                c[i][j][r2 * 2 + 1] = __float_as_int(d1);
                unsigned kg0 = (unsigned)(kBase + colL);
                unsigned long long k0 = ((unsigned long long)__float_as_uint(d0) << 32) | kg0;
                unsigned long long k1 = ((unsigned long long)__float_as_uint(d1) << 32) | (kg0 + 1);
                if (k0 < best) best = k0;
                if (k1 < best) best = k1;
            }
#pragma unroll
            for (int m = 1; m < 4; m <<= 1) {
                unsigned long long o = __shfl_xor_sync(0xFFFFFFFFu, best, m);
                if (o < best) best = o;
            }
            if (tig == 0) atomicMin(&rowKey[rowL], best);
        }
    }
    __syncthreads();
    if (tid < 128) {
        unsigned long long mine = rowKey[tid];
        unsigned long long old = atomicMin(&g_key[nBase + tid], mine);
        rowKey[tid] = (old < mine) ? old : mine;
    }
    __syncthreads();

    // ---- epilogue pass 2: append candidates below (best-known min) + MARGIN ----
#pragma unroll
    for (int i = 0; i < 2; i++) {
#pragma unroll
        for (int r2 = 0; r2 < 2; r2++) {
            int rowL = warp_m * 32 + i * 16 + gid + r2 * 8;
            int rowG = nBase + rowL;
            float thr = __uint_as_float((unsigned)(rowKey[rowL] >> 32)) + MARGIN;
#pragma unroll
            for (int j = 0; j < 8; j++) {
                int colL = warp_n * 64 + j * 8 + tig * 2;
#pragma unroll
                for (int v = 0; v < 2; v++) {
                    float d = __int_as_float(c[i][j][r2 * 2 + v]);
                    if (d < thr) {
                        int p = atomicAdd(&g_ccnt[rowG], 1);
                        if (p < CMAX)
                            g_cand[(size_t)rowG * CMAX + p] =
                                ((unsigned long long)__float_as_uint(d) << 32) |
                                (unsigned)(kBase + colL + v);
                    }
                }
            }
        }
    }
}

// ---------------- fixup + full row update, warp-per-row (row half) ----------------
__global__ __launch_bounds__(256)
void fixup_update_kernel(const float* __restrict__ cb, const float* __restrict__ x,
                         float* __restrict__ xq, float* __restrict__ idx_out,
                         int q, int rBase) {
    __shared__ float s_dist[8][CMAX];
    __shared__ alignas(16) float sres[8][D_];

    const int tid = threadIdx.x;
    const int wid = tid >> 5;
    const int lane = tid & 31;
    const int r = rBase + blockIdx.x * 8 + wid;

    const float4* res4 = reinterpret_cast<const float4*>(g_res + (size_t)r * D_);
    float4 rv[4];
#pragma unroll
    for (int i = 0; i < 4; i++) rv[i] = res4[lane + i * 32];

    unsigned long long gk = g_key[r];
    int nc = min(g_ccnt[r], CMAX);
    float thr = __uint_as_float((unsigned)(gk >> 32)) + MARGIN;
    float rn2 = g_rn2[r];

    int kbest;
    if (nc <= 1) {
        kbest = (int)(unsigned)(gk & 0xFFFFFFFFull);
    } else {
        // pass A: warp-parallel fp32 approx distance per candidate
        float bestd = 3.4e38f;
        for (int ci = 0; ci < nc; ci++) {
            unsigned long long cd = g_cand[(size_t)r * CMAX + ci];
            float cdist = __uint_as_float((unsigned)(cd >> 32));
            if (cdist >= thr) { if (lane == 0) s_dist[wid][ci] = 3.4e38f; continue; }
            int k = (int)(unsigned)(cd & 0xFFFFFFFFull);
            const float4* crow = reinterpret_cast<const float4*>(cb + (size_t)k * D_);
            float dot = 0.0f;
#pragma unroll
            for (int i = 0; i < 4; i++) {
                float4 e = crow[lane + i * 32];
                dot += rv[i].x * e.x + rv[i].y * e.y + rv[i].z * e.z + rv[i].w * e.w;
            }
#pragma unroll
            for (int off = 16; off > 0; off >>= 1)
                dot += __shfl_xor_sync(0xFFFFFFFFu, dot, off);
            float da = rn2 + __ldg(&g_en2[q * K_ + k]) - 2.0f * dot;
            if (lane == 0) s_dist[wid][ci] = da;
            if (da < bestd) bestd = da;
        }
        __syncwarp();
        // pass B: tie set = candidates within TIE of approx best
        int tcnt = 0, tfirst = -1;
        for (int ci = lane; ci < nc; ci += 32) {
            if (s_dist[wid][ci] < bestd + TIE) { tcnt++; tfirst = ci; }
        }
#pragma unroll
        for (int off = 16; off > 0; off >>= 1) {
            tcnt += __shfl_xor_sync(0xFFFFFFFFu, tcnt, off);
            int o = __shfl_xor_sync(0xFFFFFFFFu, tfirst, off);
            if (o >= 0 && (tfirst < 0)) tfirst = o;
        }
        if (tcnt == 1) {
            unsigned long long cd = g_cand[(size_t)r * CMAX + tfirst];
            kbest = (int)(unsigned)(cd & 0xFFFFFFFFull);
        } else {
            // rare: exact ascending-d sequential fmaf chain (R1 bits) per tie
#pragma unroll
            for (int i = 0; i < 4; i++)
                reinterpret_cast<float4*>(sres[wid])[lane + i * 32] = rv[i];
            __syncwarp();
            unsigned long long best = ~0ull;
            for (int ci = 0; ci < nc; ci++) {
                if (s_dist[wid][ci] >= bestd + TIE) continue;
                unsigned long long cd = g_cand[(size_t)r * CMAX + ci];
                int k = (int)(unsigned)(cd & 0xFFFFFFFFull);
                if (lane == 0) {
                    const float* crow = cb + (size_t)k * D_;
                    float dot = 0.0f;
#pragma unroll 8
                    for (int d = 0; d < D_; d++)
                        dot = fmaf(sres[wid][d], __ldg(crow + d), dot);
                    float dist = (rn2 + g_en2[q * K_ + k]) - 2.0f * dot;
                    unsigned long long key =
                        ((unsigned long long)__float_as_uint(dist) << 32) | (unsigned)k;
                    if (key < best) best = key;
                }
            }
            best = __shfl_sync(0xFFFFFFFFu, best, 0);
            kbest = (int)(unsigned)(best & 0xFFFFFFFFull);
        }
    }

    // residual update + reductions
    const float4* e4 = reinterpret_cast<const float4*>(cb + (size_t)kbest * D_);
    float4 nr[4];
    float ss = 0.0f, am = 0.0f;
#pragma unroll
    for (int i = 0; i < 4; i++) {
        float4 e = e4[lane + i * 32];
        nr[i] = make_float4(rv[i].x - e.x, rv[i].y - e.y, rv[i].z - e.z, rv[i].w - e.w);
        ss += nr[i].x * nr[i].x + nr[i].y * nr[i].y + nr[i].z * nr[i].z + nr[i].w * nr[i].w;
        am = fmaxf(am, fmaxf(fmaxf(fabsf(nr[i].x), fabsf(nr[i].y)),
                             fmaxf(fabsf(nr[i].z), fabsf(nr[i].w))));
    }
#pragma unroll
    for (int off = 16; off > 0; off >>= 1) {
        ss += __shfl_xor_sync(0xFFFFFFFFu, ss, off);
        am = fmaxf(am, __shfl_xor_sync(0xFFFFFFFFu, am, off));
    }

    if (q < Q_ - 1) {
        float4* orow = reinterpret_cast<float4*>(g_res + (size_t)r * D_);
        float inv = (am > 0.0f) ? 127.0f / am : 0.0f;
        char4* qrow = reinterpret_cast<char4*>(g_qres + (size_t)r * D_);
#pragma unroll
        for (int i = 0; i < 4; i++) {
            orow[lane + i * 32] = nr[i];
            char4 c;
            c.x = q8(nr[i].x, inv); c.y = q8(nr[i].y, inv);
            c.z = q8(nr[i].z, inv); c.w = q8(nr[i].w, inv);
            qrow[lane + i * 32] = c;
        }
        if (lane == 0) {
            g_rn2[r] = ss;
            g_sa[r] = am / 127.0f;
            g_ccnt[r] = 0;
            g_key[r] = ~0ull;
        }
    } else {
        const float4* x4 = reinterpret_cast<const float4*>(x + (size_t)r * D_);
        float4* o4 = reinterpret_cast<float4*>(xq + (size_t)r * D_);
#pragma unroll
        for (int i = 0; i < 4; i++) {
            float4 xv = x4[lane + i * 32];
            o4[lane + i * 32] = make_float4(xv.x - nr[i].x, xv.y - nr[i].y,
                                            xv.z - nr[i].z, xv.w - nr[i].w);
        }
    }
    if (lane == 0) {
        idx_out[(size_t)r * Q_ + q] = (float)kbest;
        atomicAdd(&g_lossp[(q << 6) | (r & 63)], (double)ss);
    }
}

// ---------------- finalize mean loss ----------------
__global__ void finalize_kernel(float* __restrict__ loss_out) {
    if (threadIdx.x == 0) {
        double s = 0.0;
        for (int i = 0; i < 256; i++) s += g_lossp[i];
        double ml = (s * 1.25 / ((double)N_ * (double)D_)) / (double)Q_;
        *loss_out = (float)ml;
    }
}

// ---------------- launch: two independent row-half chains, forked in the graph ----
extern "C" void kernel_launch(void* const* d_in, const int* in_sizes, int n_in,
                              void* d_out, int out_size) {
    const float* x = (const float*)d_in[0];
    const float* cbs = (const float*)d_in[1];
    float* out = (float*)d_out;
    float* xq = out;                                  // [N, D]
    float* loss_out = out + (size_t)N_ * D_;          // scalar
    float* idx_out = out + (size_t)N_ * D_ + 1;       // [N, Q] as float

    // lazily-created side stream + events (first call is the uncaptured
    // correctness run; the capture call reuses them — no allocs, no syncs)
    static cudaStream_t s2 = nullptr;
    static cudaEvent_t eFork = nullptr, eJoin = nullptr;
    if (s2 == nullptr) {
        cudaStreamCreateWithFlags(&s2, cudaStreamNonBlocking);
        cudaEventCreateWithFlags(&eFork, cudaEventDisableTiming);
        cudaEventCreateWithFlags(&eJoin, cudaEventDisableTiming);
    }

    prep_kernel<<<N_ / 8, 256>>>(x);
    cbfuse_kernel<<<(Q_ * K_) / 8, 256>>>(cbs);

    cudaEventRecord(eFork, 0);
    cudaStreamWaitEvent(s2, eFork, 0);

    dim3 grid(NHALF / BM, K_ / BN);
    for (int q = 0; q < Q_; q++) {
        const float* cb = cbs + (size_t)q * K_ * D_;
        gemm_dist_kernel<<<grid, 256, 0, 0>>>(q, 0);
        fixup_update_kernel<<<NHALF / 8, 256, 0, 0>>>(cb, x, xq, idx_out, q, 0);
    }
    for (int q = 0; q < Q_; q++) {
        const float* cb = cbs + (size_t)q * K_ * D_;
        gemm_dist_kernel<<<grid, 256, 0, s2>>>(q, NHALF);
        fixup_update_kernel<<<NHALF / 8, 256, 0, s2>>>(cb, x, xq, idx_out, q, NHALF);
    }

    cudaEventRecord(eJoin, s2);
    cudaStreamWaitEvent(0, eJoin, 0);
    finalize_kernel<<<1, 32>>>(loss_out);
}

// round 13
// speedup vs baseline: 1.4312x; 1.0079x over previous
#include <cuda_runtime.h>
#include <cstdint>

// Problem constants
#define N_ 32768
#define D_ 512
#define Q_ 4
#define K_ 2048
#define NCHAIN 4
#define NPART (N_ / NCHAIN)   // 8192

// GEMM tiling (int8)
#define BM 128
#define BN 128
#define BKI 64
#define NIT (D_ / BKI)   // 8
#define STAGES 3
#define CMAX 128
#define MARGIN 16.0f
#define TIE 0.125f

// ---------------- device scratch ----------------
__device__ float g_res[N_ * D_];                    // fp32 residual (64 MB)
__device__ int8_t g_qres[N_ * D_];                  // int8 residual (16 MB)
__device__ int8_t g_qcb[Q_ * K_ * D_];              // int8 codebooks (4 MB)
__device__ float g_rn2[N_];
__device__ float g_sa[N_];
__device__ float g_en2[Q_ * K_];
__device__ float g_sb[Q_ * K_];
__device__ unsigned long long g_key[N_];            // global coarse min (dist_bits<<32)|k
__device__ unsigned long long g_cand[(size_t)N_ * CMAX];
__device__ int g_ccnt[N_];
__device__ double g_lossp[256];

// ---------------- PTX helpers ----------------
__device__ __forceinline__ void cp_async16(uint32_t saddr, const void* gaddr) {
    asm volatile("cp.async.cg.shared.global [%0], [%1], 16;" :: "r"(saddr), "l"(gaddr));
}
#define CP_COMMIT() asm volatile("cp.async.commit_group;")
#define CP_WAIT2()  asm volatile("cp.async.wait_group 2;")

__device__ __forceinline__ void ldsm4(uint32_t& r0, uint32_t& r1, uint32_t& r2, uint32_t& r3,
                                      uint32_t addr) {
    asm volatile("ldmatrix.sync.aligned.m8n8.x4.shared.b16 {%0,%1,%2,%3}, [%4];"
                 : "=r"(r0), "=r"(r1), "=r"(r2), "=r"(r3) : "r"(addr));
}
__device__ __forceinline__ void mma_s8(int* c, const uint32_t* a, const uint32_t* b) {
    asm volatile(
        "mma.sync.aligned.m16n8k32.row.col.s32.s8.s8.s32 "
        "{%0,%1,%2,%3}, {%4,%5,%6,%7}, {%8,%9}, {%0,%1,%2,%3};"
        : "+r"(c[0]), "+r"(c[1]), "+r"(c[2]), "+r"(c[3])
        : "r"(a[0]), "r"(a[1]), "r"(a[2]), "r"(a[3]), "r"(b[0]), "r"(b[1]));
}

__device__ __forceinline__ int8_t q8(float v, float inv) {
    int t = __float2int_rn(v * inv);
    t = max(-127, min(127, t));
    return (int8_t)t;
}

// ---------------- prep (per row-partition): res = x, rn2, amax, int8 quant ------
__global__ void prep_kernel(const float* __restrict__ x, int rBase) {
    int w = rBase + ((blockIdx.x * blockDim.x + threadIdx.x) >> 5);
    int lane = threadIdx.x & 31;
    const float4* row = reinterpret_cast<const float4*>(x + (size_t)w * D_);
    float4* rrow = reinterpret_cast<float4*>(g_res + (size_t)w * D_);
    float4 v[4];
    float ss = 0.0f, am = 0.0f;
#pragma unroll
    for (int i = 0; i < 4; i++) {
        v[i] = row[lane + i * 32];
        rrow[lane + i * 32] = v[i];
        ss += v[i].x * v[i].x + v[i].y * v[i].y + v[i].z * v[i].z + v[i].w * v[i].w;
        am = fmaxf(am, fmaxf(fmaxf(fabsf(v[i].x), fabsf(v[i].y)),
                             fmaxf(fabsf(v[i].z), fabsf(v[i].w))));
    }
#pragma unroll
    for (int off = 16; off > 0; off >>= 1) {
        ss += __shfl_xor_sync(0xFFFFFFFFu, ss, off);
        am = fmaxf(am, __shfl_xor_sync(0xFFFFFFFFu, am, off));
    }
    float inv = (am > 0.0f) ? 127.0f / am : 0.0f;
    char4* orow = reinterpret_cast<char4*>(g_qres + (size_t)w * D_);
#pragma unroll
    for (int i = 0; i < 4; i++) {
        char4 c;
        c.x = q8(v[i].x, inv); c.y = q8(v[i].y, inv);
        c.z = q8(v[i].z, inv); c.w = q8(v[i].w, inv);
        orow[lane + i * 32] = c;
    }
    if (lane == 0) { g_rn2[w] = ss; g_sa[w] = am / 127.0f; }
}

// ---------------- codebook: en2 + amax + int8 quant + global resets ----------------
__global__ void cbfuse_kernel(const float* __restrict__ cbs) {
    int gidx = blockIdx.x * blockDim.x + threadIdx.x;
    if (gidx < N_) { g_ccnt[gidx] = 0; g_key[gidx] = ~0ull; }
    if (gidx < 256) g_lossp[gidx] = 0.0;
    int w = gidx >> 5;
    int lane = threadIdx.x & 31;
    if (w >= Q_ * K_) return;
    const float4* row = reinterpret_cast<const float4*>(cbs + (size_t)w * D_);
    float4 v[4];
    float ss = 0.0f, am = 0.0f;
#pragma unroll
    for (int i = 0; i < 4; i++) {
        v[i] = row[lane + i * 32];
        ss += v[i].x * v[i].x + v[i].y * v[i].y + v[i].z * v[i].z + v[i].w * v[i].w;
        am = fmaxf(am, fmaxf(fmaxf(fabsf(v[i].x), fabsf(v[i].y)),
                             fmaxf(fabsf(v[i].z), fabsf(v[i].w))));
    }
#pragma unroll
    for (int off = 16; off > 0; off >>= 1) {
        ss += __shfl_xor_sync(0xFFFFFFFFu, ss, off);
        am = fmaxf(am, __shfl_xor_sync(0xFFFFFFFFu, am, off));
    }
    float inv = (am > 0.0f) ? 127.0f / am : 0.0f;
    char4* orow = reinterpret_cast<char4*>(g_qcb + (size_t)w * D_);
#pragma unroll
    for (int i = 0; i < 4; i++) {
        char4 c;
        c.x = q8(v[i].x, inv); c.y = q8(v[i].y, inv);
        c.z = q8(v[i].z, inv); c.w = q8(v[i].w, inv);
        orow[lane + i * 32] = c;
    }
    if (lane == 0) { g_en2[w] = ss; g_sb[w] = am / 127.0f; }
}

// ---------------- int8 coarse GEMM + candidate selection (row partition) ----------
__global__ __launch_bounds__(256, 2)
void gemm_dist_kernel(int q, int rBase) {
    __shared__ alignas(128) int8_t sA[STAGES][BM * BKI];
    __shared__ alignas(128) int8_t sB[STAGES][BN * BKI];
    __shared__ float s_en2[BN];
    __shared__ float s_rn2[BM];
    __shared__ float s_sa[BM];
    __shared__ float s_sb[BN];
    __shared__ unsigned long long rowKey[BM];

    const int tid = threadIdx.x;
    const int wid = tid >> 5;
    const int lane = tid & 31;
    const int warp_m = wid >> 1;
    const int warp_n = wid & 1;
    const int gid = lane >> 2;
    const int tig = lane & 3;

    const int nBase = rBase + blockIdx.x * BM;
    const int kBase = blockIdx.y * BN;

    if (tid < 128) {
        s_en2[tid] = g_en2[q * K_ + kBase + tid];
        s_sb[tid]  = g_sb[q * K_ + kBase + tid];
        s_rn2[tid] = g_rn2[nBase + tid];
        s_sa[tid]  = g_sa[nBase + tid];
        rowKey[tid] = ~0ull;
    }

    const int8_t* gA = g_qres;
    const int8_t* gB = g_qcb + (size_t)q * K_ * D_;

    uint32_t saA[STAGES], saB[STAGES];
#pragma unroll
    for (int s = 0; s < STAGES; s++) {
        saA[s] = (uint32_t)__cvta_generic_to_shared(&sA[s][0]);
        saB[s] = (uint32_t)__cvta_generic_to_shared(&sB[s][0]);
    }

    int c[2][8][4];
#pragma unroll
    for (int i = 0; i < 2; i++)
#pragma unroll
        for (int j = 0; j < 8; j++)
#pragma unroll
            for (int v = 0; v < 4; v++) c[i][j][v] = 0;

    auto load_tiles = [&](int s, int it) {
#pragma unroll
        for (int u = 0; u < 2; u++) {
            int cidx = tid + 256 * u;
            int r = cidx >> 2, ch = cidx & 3;
            uint32_t off = (uint32_t)(r * 64 + ((ch ^ (r & 3)) << 4));
            cp_async16(saA[s] + off, gA + (size_t)(nBase + r) * D_ + it * BKI + ch * 16);
            cp_async16(saB[s] + off, gB + (size_t)(kBase + r) * D_ + it * BKI + ch * 16);
        }
    };

    load_tiles(0, 0); CP_COMMIT();
    load_tiles(1, 1); CP_COMMIT();

    for (int it = 0; it < NIT; it++) {
        int buf = it % STAGES;
        // issue the prefetch first, then wait (3 groups in flight, need <=2 pending)
        if (it + 2 < NIT) { load_tiles((it + 2) % STAGES, it + 2); CP_COMMIT(); }
        CP_WAIT2();
        __syncthreads();

#pragma unroll
        for (int kk = 0; kk < 2; kk++) {
            uint32_t a[2][4], b[8][2];
#pragma unroll
            for (int i = 0; i < 2; i++) {
                int row = warp_m * 32 + i * 16 + (lane & 7) + ((lane >> 3) & 1) * 8;
                int ch = kk * 2 + (lane >> 4);
                uint32_t addr = saA[buf] + (uint32_t)(row * 64 + ((ch ^ (row & 3)) << 4));
                ldsm4(a[i][0], a[i][1], a[i][2], a[i][3], addr);
            }
#pragma unroll
            for (int p = 0; p < 4; p++) {
                int row = warp_n * 64 + p * 16 + (lane & 7) + ((lane >> 4) & 1) * 8;
                int ch = kk * 2 + ((lane >> 3) & 1);
                uint32_t addr = saB[buf] + (uint32_t)(row * 64 + ((ch ^ (row & 3)) << 4));
                ldsm4(b[2 * p][0], b[2 * p][1], b[2 * p + 1][0], b[2 * p + 1][1], addr);
            }
#pragma unroll
            for (int i = 0; i < 2; i++)
#pragma unroll
                for (int j = 0; j < 8; j++)
                    mma_s8(c[i][j], a[i], b[j]);
        }
        __syncthreads();
    }

    // ---- epilogue pass 1: dists + block-local row min ----
#pragma unroll
    for (int i = 0; i < 2; i++) {
#pragma unroll
        for (int r2 = 0; r2 < 2; r2++) {
            int rowL = warp_m * 32 + i * 16 + gid + r2 * 8;
            float rn2 = s_rn2[rowL];
            float sc2 = 2.0f * s_sa[rowL];
            unsigned long long best = ~0ull;
#pragma unroll
            for (int j = 0; j < 8; j++) {
                int colL = warp_n * 64 + j * 8 + tig * 2;
                float d0 = rn2 + s_en2[colL] - sc2 * s_sb[colL] * (float)c[i][j][r2 * 2 + 0];
                float d1 = rn2 + s_en2[colL + 1] - sc2 * s_sb[colL + 1] * (float)c[i][j][r2 * 2 + 1];
                c[i][j][r2 * 2 + 0] = __float_as_int(d0);
                c[i][j][r2 * 2 + 1] = __float_as_int(d1);
                unsigned kg0 = (unsigned)(kBase + colL);
                unsigned long long k0 = ((unsigned long long)__float_as_uint(d0) << 32) | kg0;
                unsigned long long k1 = ((unsigned long long)__float_as_uint(d1) << 32) | (kg0 + 1);
                if (k0 < best) best = k0;
                if (k1 < best) best = k1;
            }
#pragma unroll
            for (int m = 1; m < 4; m <<= 1) {
                unsigned long long o = __shfl_xor_sync(0xFFFFFFFFu, best, m);
                if (o < best) best = o;
            }
            if (tig == 0) atomicMin(&rowKey[rowL], best);
        }
    }
    __syncthreads();
    if (tid < 128) {
        unsigned long long mine = rowKey[tid];
        unsigned long long old = atomicMin(&g_key[nBase + tid], mine);
        rowKey[tid] = (old < mine) ? old : mine;
    }
    __syncthreads();

    // ---- epilogue pass 2: append candidates below (best-known min) + MARGIN ----
#pragma unroll
    for (int i = 0; i < 2; i++) {
#pragma unroll
        for (int r2 = 0; r2 < 2; r2++) {
            int rowL = warp_m * 32 + i * 16 + gid + r2 * 8;
            int rowG = nBase + rowL;
            float thr = __uint_as_float((unsigned)(rowKey[rowL] >> 32)) + MARGIN;
#pragma unroll
            for (int j = 0; j < 8; j++) {
                int colL = warp_n * 64 + j * 8 + tig * 2;
#pragma unroll
                for (int v = 0; v < 2; v++) {
                    float d = __int_as_float(c[i][j][r2 * 2 + v]);
                    if (d < thr) {
                        int p = atomicAdd(&g_ccnt[rowG], 1);
                        if (p < CMAX)
                            g_cand[(size_t)rowG * CMAX + p] =
                                ((unsigned long long)__float_as_uint(d) << 32) |
                                (unsigned)(kBase + colL + v);
                    }
                }
            }
        }
    }
}

// ---------------- fixup + full row update, warp-per-row (row partition) ------------
__global__ __launch_bounds__(256)
void fixup_update_kernel(const float* __restrict__ cb, const float* __restrict__ x,
                         float* __restrict__ xq, float* __restrict__ idx_out,
                         int q, int rBase) {
    __shared__ float s_dist[8][CMAX];
    __shared__ alignas(16) float sres[8][D_];

    const int tid = threadIdx.x;
    const int wid = tid >> 5;
    const int lane = tid & 31;
    const int r = rBase + blockIdx.x * 8 + wid;

    const float4* res4 = reinterpret_cast<const float4*>(g_res + (size_t)r * D_);
    float4 rv[4];
#pragma unroll
    for (int i = 0; i < 4; i++) rv[i] = res4[lane + i * 32];

    unsigned long long gk = g_key[r];
    int nc = min(g_ccnt[r], CMAX);
    float thr = __uint_as_float((unsigned)(gk >> 32)) + MARGIN;
    float rn2 = g_rn2[r];

    int kbest;
    if (nc <= 1) {
        kbest = (int)(unsigned)(gk & 0xFFFFFFFFull);
    } else {
        // pass A: warp-parallel fp32 approx distance per candidate
        float bestd = 3.4e38f;
        for (int ci = 0; ci < nc; ci++) {
            unsigned long long cd = g_cand[(size_t)r * CMAX + ci];
            float cdist = __uint_as_float((unsigned)(cd >> 32));
            if (cdist >= thr) { if (lane == 0) s_dist[wid][ci] = 3.4e38f; continue; }
            int k = (int)(unsigned)(cd & 0xFFFFFFFFull);
            const float4* crow = reinterpret_cast<const float4*>(cb + (size_t)k * D_);
            float dot = 0.0f;
#pragma unroll
            for (int i = 0; i < 4; i++) {
                float4 e = crow[lane + i * 32];
                dot += rv[i].x * e.x + rv[i].y * e.y + rv[i].z * e.z + rv[i].w * e.w;
            }
#pragma unroll
            for (int off = 16; off > 0; off >>= 1)
                dot += __shfl_xor_sync(0xFFFFFFFFu, dot, off);
            float da = rn2 + __ldg(&g_en2[q * K_ + k]) - 2.0f * dot;
            if (lane == 0) s_dist[wid][ci] = da;
            if (da < bestd) bestd = da;
        }
        __syncwarp();
        // pass B: tie set = candidates within TIE of approx best
        int tcnt = 0, tfirst = -1;
        for (int ci = lane; ci < nc; ci += 32) {
            if (s_dist[wid][ci] < bestd + TIE) { tcnt++; tfirst = ci; }
        }
#pragma unroll
        for (int off = 16; off > 0; off >>= 1) {
            tcnt += __shfl_xor_sync(0xFFFFFFFFu, tcnt, off);
            int o = __shfl_xor_sync(0xFFFFFFFFu, tfirst, off);
            if (o >= 0 && (tfirst < 0)) tfirst = o;
        }
        if (tcnt == 1) {
            unsigned long long cd = g_cand[(size_t)r * CMAX + tfirst];
            kbest = (int)(unsigned)(cd & 0xFFFFFFFFull);
        } else {
            // rare: exact ascending-d sequential fmaf chain (R1 bits) per tie
#pragma unroll
            for (int i = 0; i < 4; i++)
                reinterpret_cast<float4*>(sres[wid])[lane + i * 32] = rv[i];
            __syncwarp();
            unsigned long long best = ~0ull;
            for (int ci = 0; ci < nc; ci++) {
                if (s_dist[wid][ci] >= bestd + TIE) continue;
                unsigned long long cd = g_cand[(size_t)r * CMAX + ci];
                int k = (int)(unsigned)(cd & 0xFFFFFFFFull);
                if (lane == 0) {
                    const float* crow = cb + (size_t)k * D_;
                    float dot = 0.0f;
#pragma unroll 8
                    for (int d = 0; d < D_; d++)
                        dot = fmaf(sres[wid][d], __ldg(crow + d), dot);
                    float dist = (rn2 + g_en2[q * K_ + k]) - 2.0f * dot;
                    unsigned long long key =
                        ((unsigned long long)__float_as_uint(dist) << 32) | (unsigned)k;
                    if (key < best) best = key;
                }
            }
            best = __shfl_sync(0xFFFFFFFFu, best, 0);
            kbest = (int)(unsigned)(best & 0xFFFFFFFFull);
        }
    }

    // residual update + reductions
    const float4* e4 = reinterpret_cast<const float4*>(cb + (size_t)kbest * D_);
    float4 nr[4];
    float ss = 0.0f, am = 0.0f;
#pragma unroll
    for (int i = 0; i < 4; i++) {
        float4 e = e4[lane + i * 32];
        nr[i] = make_float4(rv[i].x - e.x, rv[i].y - e.y, rv[i].z - e.z, rv[i].w - e.w);
        ss += nr[i].x * nr[i].x + nr[i].y * nr[i].y + nr[i].z * nr[i].z + nr[i].w * nr[i].w;
        am = fmaxf(am, fmaxf(fmaxf(fabsf(nr[i].x), fabsf(nr[i].y)),
                             fmaxf(fabsf(nr[i].z), fabsf(nr[i].w))));
    }
#pragma unroll
    for (int off = 16; off > 0; off >>= 1) {
        ss += __shfl_xor_sync(0xFFFFFFFFu, ss, off);
        am = fmaxf(am, __shfl_xor_sync(0xFFFFFFFFu, am, off));
    }

    if (q < Q_ - 1) {
        float4* orow = reinterpret_cast<float4*>(g_res + (size_t)r * D_);
        float inv = (am > 0.0f) ? 127.0f / am : 0.0f;
        char4* qrow = reinterpret_cast<char4*>(g_qres + (size_t)r * D_);
#pragma unroll
        for (int i = 0; i < 4; i++) {
            orow[lane + i * 32] = nr[i];
            char4 c;
            c.x = q8(nr[i].x, inv); c.y = q8(nr[i].y, inv);
            c.z = q8(nr[i].z, inv); c.w = q8(nr[i].w, inv);
            qrow[lane + i * 32] = c;
        }
        if (lane == 0) {
            g_rn2[r] = ss;
            g_sa[r] = am / 127.0f;
            g_ccnt[r] = 0;
            g_key[r] = ~0ull;
        }
    } else {
        const float4* x4 = reinterpret_cast<const float4*>(x + (size_t)r * D_);
        float4* o4 = reinterpret_cast<float4*>(xq + (size_t)r * D_);
#pragma unroll
        for (int i = 0; i < 4; i++) {
            float4 xv = x4[lane + i * 32];
            o4[lane + i * 32] = make_float4(xv.x - nr[i].x, xv.y - nr[i].y,
                                            xv.z - nr[i].z, xv.w - nr[i].w);
        }
    }
    if (lane == 0) {
        idx_out[(size_t)r * Q_ + q] = (float)kbest;
        atomicAdd(&g_lossp[(q << 6) | (r & 63)], (double)ss);
    }
}

// ---------------- finalize mean loss ----------------
__global__ void finalize_kernel(float* __restrict__ loss_out) {
    if (threadIdx.x == 0) {
        double s = 0.0;
        for (int i = 0; i < 256; i++) s += g_lossp[i];
        double ml = (s * 1.25 / ((double)N_ * (double)D_)) / (double)Q_;
        *loss_out = (float)ml;
    }
}

// ---------------- launch: four independent row-quarter chains in the graph -------
extern "C" void kernel_launch(void* const* d_in, const int* in_sizes, int n_in,
                              void* d_out, int out_size) {
    const float* x = (const float*)d_in[0];
    const float* cbs = (const float*)d_in[1];
    float* out = (float*)d_out;
    float* xq = out;                                  // [N, D]
    float* loss_out = out + (size_t)N_ * D_;          // scalar
    float* idx_out = out + (size_t)N_ * D_ + 1;       // [N, Q] as float

    // lazily-created side streams + events (created on the uncaptured
    // correctness call; capture sees only launches + event edges)
    static cudaStream_t st[NCHAIN] = {nullptr, nullptr, nullptr, nullptr};
    static cudaEvent_t eFork = nullptr, eJoin[NCHAIN] = {nullptr, nullptr, nullptr, nullptr};
    if (st[1] == nullptr) {
        st[0] = 0;   // legacy default stream for chain 0
        for (int i = 1; i < NCHAIN; i++)
            cudaStreamCreateWithFlags(&st[i], cudaStreamNonBlocking);
        cudaEventCreateWithFlags(&eFork, cudaEventDisableTiming);
        for (int i = 1; i < NCHAIN; i++)
            cudaEventCreateWithFlags(&eJoin[i], cudaEventDisableTiming);
    }

    cbfuse_kernel<<<(Q_ * K_) / 8, 256>>>(cbs);
    cudaEventRecord(eFork, 0);
    for (int i = 1; i < NCHAIN; i++) cudaStreamWaitEvent(st[i], eFork, 0);

    dim3 grid(NPART / BM, K_ / BN);
    for (int i = 0; i < NCHAIN; i++) {
        int rBase = i * NPART;
        prep_kernel<<<NPART / 8, 256, 0, st[i]>>>(x, rBase);
        for (int q = 0; q < Q_; q++) {
            const float* cb = cbs + (size_t)q * K_ * D_;
            gemm_dist_kernel<<<grid, 256, 0, st[i]>>>(q, rBase);
            fixup_update_kernel<<<NPART / 8, 256, 0, st[i]>>>(cb, x, xq, idx_out, q, rBase);
        }
    }

    for (int i = 1; i < NCHAIN; i++) {
        cudaEventRecord(eJoin[i], st[i]);
        cudaStreamWaitEvent(0, eJoin[i], 0);
    }
    finalize_kernel<<<1, 32>>>(loss_out);
}

// round 15
// speedup vs baseline: 1.4340x; 1.0020x over previous
#include <cuda_runtime.h>
#include <cstdint>

// Problem constants
#define N_ 32768
#define D_ 512
#define Q_ 4
#define K_ 2048
#define NCHAIN 4
#define NPART (N_ / NCHAIN)   // 8192

// GEMM tiling (int8)
#define BM 128
#define BN 128
#define BKI 64
#define NIT (D_ / BKI)   // 8
#define STAGES 3
#define CMAX 128
#define MARGIN 16.0f
#define TIE 0.125f

// ---------------- device scratch ----------------
__device__ float g_res[N_ * D_];                    // fp32 residual (64 MB)
__device__ int8_t g_qres[N_ * D_];                  // int8 residual (16 MB)
__device__ int8_t g_qcb[Q_ * K_ * D_];              // int8 codebooks (4 MB)
__device__ float g_rn2[N_];
__device__ float g_sa[N_];
__device__ float g_en2[Q_ * K_];
__device__ float g_sb[Q_ * K_];
__device__ unsigned long long g_key[N_];            // global coarse min (dist_bits<<32)|k
__device__ unsigned long long g_cand[(size_t)N_ * CMAX];
__device__ int g_ccnt[N_];
__device__ double g_lossp[256];

// ---------------- PTX helpers ----------------
__device__ __forceinline__ void cp_async16(uint32_t saddr, const void* gaddr) {
    asm volatile("cp.async.cg.shared.global [%0], [%1], 16;" :: "r"(saddr), "l"(gaddr));
}
#define CP_COMMIT() asm volatile("cp.async.commit_group;")
#define CP_WAIT1()  asm volatile("cp.async.wait_group 1;")

__device__ __forceinline__ void ldsm4(uint32_t& r0, uint32_t& r1, uint32_t& r2, uint32_t& r3,
                                      uint32_t addr) {
    asm volatile("ldmatrix.sync.aligned.m8n8.x4.shared.b16 {%0,%1,%2,%3}, [%4];"
                 : "=r"(r0), "=r"(r1), "=r"(r2), "=r"(r3) : "r"(addr));
}
__device__ __forceinline__ void mma_s8(int* c, const uint32_t* a, const uint32_t* b) {
    asm volatile(
        "mma.sync.aligned.m16n8k32.row.col.s32.s8.s8.s32 "
        "{%0,%1,%2,%3}, {%4,%5,%6,%7}, {%8,%9}, {%0,%1,%2,%3};"
        : "+r"(c[0]), "+r"(c[1]), "+r"(c[2]), "+r"(c[3])
        : "r"(a[0]), "r"(a[1]), "r"(a[2]), "r"(a[3]), "r"(b[0]), "r"(b[1]));
}

__device__ __forceinline__ int8_t q8(float v, float inv) {
    int t = __float2int_rn(v * inv);
    t = max(-127, min(127, t));
    return (int8_t)t;
}

// ---------------- prep (per row-partition): res = x, rn2, amax, int8 quant ------
__global__ void prep_kernel(const float* __restrict__ x, int rBase) {
    int w = rBase + ((blockIdx.x * blockDim.x + threadIdx.x) >> 5);
    int lane = threadIdx.x & 31;
    const float4* row = reinterpret_cast<const float4*>(x + (size_t)w * D_);
    float4* rrow = reinterpret_cast<float4*>(g_res + (size_t)w * D_);
    float4 v[4];
    float ss = 0.0f, am = 0.0f;
#pragma unroll
    for (int i = 0; i < 4; i++) {
        v[i] = row[lane + i * 32];
        rrow[lane + i * 32] = v[i];
        ss += v[i].x * v[i].x + v[i].y * v[i].y + v[i].z * v[i].z + v[i].w * v[i].w;
        am = fmaxf(am, fmaxf(fmaxf(fabsf(v[i].x), fabsf(v[i].y)),
                             fmaxf(fabsf(v[i].z), fabsf(v[i].w))));
    }
#pragma unroll
    for (int off = 16; off > 0; off >>= 1) {
        ss += __shfl_xor_sync(0xFFFFFFFFu, ss, off);
        am = fmaxf(am, __shfl_xor_sync(0xFFFFFFFFu, am, off));
    }
    float inv = (am > 0.0f) ? 127.0f / am : 0.0f;
    char4* orow = reinterpret_cast<char4*>(g_qres + (size_t)w * D_);
#pragma unroll
    for (int i = 0; i < 4; i++) {
        char4 c;
        c.x = q8(v[i].x, inv); c.y = q8(v[i].y, inv);
        c.z = q8(v[i].z, inv); c.w = q8(v[i].w, inv);
        orow[lane + i * 32] = c;
    }
    if (lane == 0) { g_rn2[w] = ss; g_sa[w] = am / 127.0f; }
}

// ---------------- codebook: en2 + amax + int8 quant + global resets ----------------
__global__ void cbfuse_kernel(const float* __restrict__ cbs) {
    int gidx = blockIdx.x * blockDim.x + threadIdx.x;
    if (gidx < N_) { g_ccnt[gidx] = 0; g_key[gidx] = ~0ull; }
    if (gidx < 256) g_lossp[gidx] = 0.0;
    int w = gidx >> 5;
    int lane = threadIdx.x & 31;
    if (w >= Q_ * K_) return;
    const float4* row = reinterpret_cast<const float4*>(cbs + (size_t)w * D_);
    float4 v[4];
    float ss = 0.0f, am = 0.0f;
#pragma unroll
    for (int i = 0; i < 4; i++) {
        v[i] = row[lane + i * 32];
        ss += v[i].x * v[i].x + v[i].y * v[i].y + v[i].z * v[i].z + v[i].w * v[i].w;
        am = fmaxf(am, fmaxf(fmaxf(fabsf(v[i].x), fabsf(v[i].y)),
                             fmaxf(fabsf(v[i].z), fabsf(v[i].w))));
    }
#pragma unroll
    for (int off = 16; off > 0; off >>= 1) {
        ss += __shfl_xor_sync(0xFFFFFFFFu, ss, off);
        am = fmaxf(am, __shfl_xor_sync(0xFFFFFFFFu, am, off));
    }
    float inv = (am > 0.0f) ? 127.0f / am : 0.0f;
    char4* orow = reinterpret_cast<char4*>(g_qcb + (size_t)w * D_);
#pragma unroll
    for (int i = 0; i < 4; i++) {
        char4 c;
        c.x = q8(v[i].x, inv); c.y = q8(v[i].y, inv);
        c.z = q8(v[i].z, inv); c.w = q8(v[i].w, inv);
        orow[lane + i * 32] = c;
    }
    if (lane == 0) { g_en2[w] = ss; g_sb[w] = am / 127.0f; }
}

// ---------------- int8 coarse GEMM + candidate selection (row partition) ----------
// 3-stage cp.async ring, prefetch issued AFTER the barrier (race-free; R5-R12 proven).
__global__ __launch_bounds__(256, 2)
void gemm_dist_kernel(int q, int rBase) {
    __shared__ alignas(128) int8_t sA[STAGES][BM * BKI];
    __shared__ alignas(128) int8_t sB[STAGES][BN * BKI];
    __shared__ float s_en2[BN];
    __shared__ float s_rn2[BM];
    __shared__ float s_sa[BM];
    __shared__ float s_sb[BN];
    __shared__ unsigned long long rowKey[BM];

    const int tid = threadIdx.x;
    const int wid = tid >> 5;
    const int lane = tid & 31;
    const int warp_m = wid >> 1;
    const int warp_n = wid & 1;
    const int gid = lane >> 2;
    const int tig = lane & 3;

    const int nBase = rBase + blockIdx.x * BM;
    const int kBase = blockIdx.y * BN;

    if (tid < 128) {
        s_en2[tid] = g_en2[q * K_ + kBase + tid];
        s_sb[tid]  = g_sb[q * K_ + kBase + tid];
        s_rn2[tid] = g_rn2[nBase + tid];
        s_sa[tid]  = g_sa[nBase + tid];
        rowKey[tid] = ~0ull;
    }

    const int8_t* gA = g_qres;
    const int8_t* gB = g_qcb + (size_t)q * K_ * D_;

    uint32_t saA[STAGES], saB[STAGES];
#pragma unroll
    for (int s = 0; s < STAGES; s++) {
        saA[s] = (uint32_t)__cvta_generic_to_shared(&sA[s][0]);
        saB[s] = (uint32_t)__cvta_generic_to_shared(&sB[s][0]);
    }

    int c[2][8][4];
#pragma unroll
    for (int i = 0; i < 2; i++)
#pragma unroll
        for (int j = 0; j < 8; j++)
#pragma unroll
            for (int v = 0; v < 4; v++) c[i][j][v] = 0;

    auto load_tiles = [&](int s, int it) {
#pragma unroll
        for (int u = 0; u < 2; u++) {
            int cidx = tid + 256 * u;
            int r = cidx >> 2, ch = cidx & 3;
            uint32_t off = (uint32_t)(r * 64 + ((ch ^ (r & 3)) << 4));
            cp_async16(saA[s] + off, gA + (size_t)(nBase + r) * D_ + it * BKI + ch * 16);
            cp_async16(saB[s] + off, gB + (size_t)(kBase + r) * D_ + it * BKI + ch * 16);
        }
    };

    load_tiles(0, 0); CP_COMMIT();
    load_tiles(1, 1); CP_COMMIT();

    for (int it = 0; it < NIT; it++) {
        int buf = it % STAGES;
        CP_WAIT1();
        __syncthreads();                 // all warps done with it-1's slot; group it ready
        if (it + 2 < NIT) load_tiles((it + 2) % STAGES, it + 2);
        CP_COMMIT();

#pragma unroll
        for (int kk = 0; kk < 2; kk++) {
            uint32_t a[2][4], b[8][2];
#pragma unroll
            for (int i = 0; i < 2; i++) {
                int row = warp_m * 32 + i * 16 + (lane & 7) + ((lane >> 3) & 1) * 8;
                int ch = kk * 2 + (lane >> 4);
                uint32_t addr = saA[buf] + (uint32_t)(row * 64 + ((ch ^ (row & 3)) << 4));
                ldsm4(a[i][0], a[i][1], a[i][2], a[i][3], addr);
            }
#pragma unroll
            for (int p = 0; p < 4; p++) {
                int row = warp_n * 64 + p * 16 + (lane & 7) + ((lane >> 4) & 1) * 8;
                int ch = kk * 2 + ((lane >> 3) & 1);
                uint32_t addr = saB[buf] + (uint32_t)(row * 64 + ((ch ^ (row & 3)) << 4));
                ldsm4(b[2 * p][0], b[2 * p][1], b[2 * p + 1][0], b[2 * p + 1][1], addr);
            }
#pragma unroll
            for (int i = 0; i < 2; i++)
#pragma unroll
                for (int j = 0; j < 8; j++)
                    mma_s8(c[i][j], a[i], b[j]);
        }
    }

    // ---- epilogue pass 1: dists + block-local row min ----
#pragma unroll
    for (int i = 0; i < 2; i++) {
#pragma unroll
        for (int r2 = 0; r2 < 2; r2++) {
            int rowL = warp_m * 32 + i * 16 + gid + r2 * 8;
            float rn2 = s_rn2[rowL];
            float sc2 = 2.0f * s_sa[rowL];
            unsigned long long best = ~0ull;
#pragma unroll
            for (int j = 0; j < 8; j++) {
                int colL = warp_n * 64 + j * 8 + tig * 2;
                float d0 = rn2 + s_en2[colL] - sc2 * s_sb[colL] * (float)c[i][j][r2 * 2 + 0];
                float d1 = rn2 + s_en2[colL + 1] - sc2 * s_sb[colL + 1] * (float)c[i][j][r2 * 2 + 1];
                c[i][j][r2 * 2 + 0] = __float_as_int(d0);
                c[i][j][r2 * 2 + 1] = __float_as_int(d1);
                unsigned kg0 = (unsigned)(kBase + colL);
                unsigned long long k0 = ((unsigned long long)__float_as_uint(d0) << 32) | kg0;
                unsigned long long k1 = ((unsigned long long)__float_as_uint(d1) << 32) | (kg0 + 1);
                if (k0 < best) best = k0;
                if (k1 < best) best = k1;
            }
#pragma unroll
            for (int m = 1; m < 4; m <<= 1) {
                unsigned long long o = __shfl_xor_sync(0xFFFFFFFFu, best, m);
                if (o < best) best = o;
            }
            if (tig == 0) atomicMin(&rowKey[rowL], best);
        }
    }
    __syncthreads();
    if (tid < 128) {
        unsigned long long mine = rowKey[tid];
        unsigned long long old = atomicMin(&g_key[nBase + tid], mine);
        rowKey[tid] = (old < mine) ? old : mine;
    }
    __syncthreads();

    // ---- epilogue pass 2: append candidates below (best-known min) + MARGIN ----
#pragma unroll
    for (int i = 0; i < 2; i++) {
#pragma unroll
        for (int r2 = 0; r2 < 2; r2++) {
            int rowL = warp_m * 32 + i * 16 + gid + r2 * 8;
            int rowG = nBase + rowL;
            float thr = __uint_as_float((unsigned)(rowKey[rowL] >> 32)) + MARGIN;
#pragma unroll
            for (int j = 0; j < 8; j++) {
                int colL = warp_n * 64 + j * 8 + tig * 2;
#pragma unroll
                for (int v = 0; v < 2; v++) {
                    float d = __int_as_float(c[i][j][r2 * 2 + v]);
                    if (d < thr) {
                        int p = atomicAdd(&g_ccnt[rowG], 1);
                        if (p < CMAX)
                            g_cand[(size_t)rowG * CMAX + p] =
                                ((unsigned long long)__float_as_uint(d) << 32) |
                                (unsigned)(kBase + colL + v);
                    }
                }
            }
        }
    }
}

// ---------------- fixup + full row update, warp-per-row (row partition) ------------
__global__ __launch_bounds__(256)
void fixup_update_kernel(const float* __restrict__ cb, const float* __restrict__ x,
                         float* __restrict__ xq, float* __restrict__ idx_out,
                         int q, int rBase) {
    __shared__ float s_dist[8][CMAX];
    __shared__ alignas(16) float sres[8][D_];

    const int tid = threadIdx.x;
    const int wid = tid >> 5;
    const int lane = tid & 31;
    const int r = rBase + blockIdx.x * 8 + wid;

    const float4* res4 = reinterpret_cast<const float4*>(g_res + (size_t)r * D_);
    float4 rv[4];
#pragma unroll
    for (int i = 0; i < 4; i++) rv[i] = res4[lane + i * 32];

    unsigned long long gk = g_key[r];
    int nc = min(g_ccnt[r], CMAX);
    float thr = __uint_as_float((unsigned)(gk >> 32)) + MARGIN;
    float rn2 = g_rn2[r];

    int kbest;
    if (nc <= 1) {
        kbest = (int)(unsigned)(gk & 0xFFFFFFFFull);
    } else {
        // pass A: warp-parallel fp32 approx distance per candidate
        float bestd = 3.4e38f;
        for (int ci = 0; ci < nc; ci++) {
            unsigned long long cd = g_cand[(size_t)r * CMAX + ci];
            float cdist = __uint_as_float((unsigned)(cd >> 32));
            if (cdist >= thr) { if (lane == 0) s_dist[wid][ci] = 3.4e38f; continue; }
            int k = (int)(unsigned)(cd & 0xFFFFFFFFull);
            const float4* crow = reinterpret_cast<const float4*>(cb + (size_t)k * D_);
            float dot = 0.0f;
#pragma unroll
            for (int i = 0; i < 4; i++) {
                float4 e = crow[lane + i * 32];
                dot += rv[i].x * e.x + rv[i].y * e.y + rv[i].z * e.z + rv[i].w * e.w;
            }
#pragma unroll
            for (int off = 16; off > 0; off >>= 1)
                dot += __shfl_xor_sync(0xFFFFFFFFu, dot, off);
            float da = rn2 + __ldg(&g_en2[q * K_ + k]) - 2.0f * dot;
            if (lane == 0) s_dist[wid][ci] = da;
            if (da < bestd) bestd = da;
        }
        __syncwarp();
        // pass B: tie set = candidates within TIE of approx best
        int tcnt = 0, tfirst = -1;
        for (int ci = lane; ci < nc; ci += 32) {
            if (s_dist[wid][ci] < bestd + TIE) { tcnt++; tfirst = ci; }
        }
#pragma unroll
        for (int off = 16; off > 0; off >>= 1) {
            tcnt += __shfl_xor_sync(0xFFFFFFFFu, tcnt, off);
            int o = __shfl_xor_sync(0xFFFFFFFFu, tfirst, off);
            if (o >= 0 && (tfirst < 0)) tfirst = o;
        }
        if (tcnt == 1) {
            unsigned long long cd = g_cand[(size_t)r * CMAX + tfirst];
            kbest = (int)(unsigned)(cd & 0xFFFFFFFFull);
        } else {
            // rare: exact ascending-d sequential fmaf chain (R1 bits) per tie
#pragma unroll
            for (int i = 0; i < 4; i++)
                reinterpret_cast<float4*>(sres[wid])[lane + i * 32] = rv[i];
            __syncwarp();
            unsigned long long best = ~0ull;
            for (int ci = 0; ci < nc; ci++) {
                if (s_dist[wid][ci] >= bestd + TIE) continue;
                unsigned long long cd = g_cand[(size_t)r * CMAX + ci];
                int k = (int)(unsigned)(cd & 0xFFFFFFFFull);
                if (lane == 0) {
                    const float* crow = cb + (size_t)k * D_;
                    float dot = 0.0f;
#pragma unroll 8
                    for (int d = 0; d < D_; d++)
                        dot = fmaf(sres[wid][d], __ldg(crow + d), dot);
                    float dist = (rn2 + g_en2[q * K_ + k]) - 2.0f * dot;
                    unsigned long long key =
                        ((unsigned long long)__float_as_uint(dist) << 32) | (unsigned)k;
                    if (key < best) best = key;
                }
            }
            best = __shfl_sync(0xFFFFFFFFu, best, 0);
            kbest = (int)(unsigned)(best & 0xFFFFFFFFull);
        }
    }

    // residual update + reductions
    const float4* e4 = reinterpret_cast<const float4*>(cb + (size_t)kbest * D_);
    float4 nr[4];
    float ss = 0.0f, am = 0.0f;
#pragma unroll
    for (int i = 0; i < 4; i++) {
        float4 e = e4[lane + i * 32];
        nr[i] = make_float4(rv[i].x - e.x, rv[i].y - e.y, rv[i].z - e.z, rv[i].w - e.w);
        ss += nr[i].x * nr[i].x + nr[i].y * nr[i].y + nr[i].z * nr[i].z + nr[i].w * nr[i].w;
        am = fmaxf(am, fmaxf(fmaxf(fabsf(nr[i].x), fabsf(nr[i].y)),
                             fmaxf(fabsf(nr[i].z), fabsf(nr[i].w))));
    }
#pragma unroll
    for (int off = 16; off > 0; off >>= 1) {
        ss += __shfl_xor_sync(0xFFFFFFFFu, ss, off);
        am = fmaxf(am, __shfl_xor_sync(0xFFFFFFFFu, am, off));
    }

    if (q < Q_ - 1) {
        float4* orow = reinterpret_cast<float4*>(g_res + (size_t)r * D_);
        float inv = (am > 0.0f) ? 127.0f / am : 0.0f;
        char4* qrow = reinterpret_cast<char4*>(g_qres + (size_t)r * D_);
#pragma unroll
        for (int i = 0; i < 4; i++) {
            orow[lane + i * 32] = nr[i];
            char4 c;
            c.x = q8(nr[i].x, inv); c.y = q8(nr[i].y, inv);
            c.z = q8(nr[i].z, inv); c.w = q8(nr[i].w, inv);
            qrow[lane + i * 32] = c;
        }
        if (lane == 0) {
            g_rn2[r] = ss;
            g_sa[r] = am / 127.0f;
            g_ccnt[r] = 0;
            g_key[r] = ~0ull;
        }
    } else {
        const float4* x4 = reinterpret_cast<const float4*>(x + (size_t)r * D_);
        float4* o4 = reinterpret_cast<float4*>(xq + (size_t)r * D_);
#pragma unroll
        for (int i = 0; i < 4; i++) {
            float4 xv = x4[lane + i * 32];
            o4[lane + i * 32] = make_float4(xv.x - nr[i].x, xv.y - nr[i].y,
                                            xv.z - nr[i].z, xv.w - nr[i].w);
        }
    }
    if (lane == 0) {
        idx_out[(size_t)r * Q_ + q] = (float)kbest;
        atomicAdd(&g_lossp[(q << 6) | (r & 63)], (double)ss);
    }
}

// ---------------- finalize mean loss ----------------
__global__ void finalize_kernel(float* __restrict__ loss_out) {
    if (threadIdx.x == 0) {
        double s = 0.0;
        for (int i = 0; i < 256; i++) s += g_lossp[i];
        double ml = (s * 1.25 / ((double)N_ * (double)D_)) / (double)Q_;
        *loss_out = (float)ml;
    }
}

// ---------------- launch: four independent row-quarter chains in the graph -------
// Stream topology identical to the R13 config that passed the teardown check:
// chain 0 on the legacy default stream; three created side streams.
extern "C" void kernel_launch(void* const* d_in, const int* in_sizes, int n_in,
                              void* d_out, int out_size) {
    const float* x = (const float*)d_in[0];
    const float* cbs = (const float*)d_in[1];
    float* out = (float*)d_out;
    float* xq = out;                                  // [N, D]
    float* loss_out = out + (size_t)N_ * D_;          // scalar
    float* idx_out = out + (size_t)N_ * D_ + 1;       // [N, Q] as float

    static cudaStream_t st[NCHAIN] = {nullptr, nullptr, nullptr, nullptr};
    static cudaEvent_t eFork = nullptr, eCb = nullptr;
    static cudaEvent_t eJoin[NCHAIN] = {nullptr, nullptr, nullptr, nullptr};
    if (st[1] == nullptr) {
        st[0] = 0;   // legacy default stream for chain 0
        for (int i = 1; i < NCHAIN; i++)
            cudaStreamCreateWithFlags(&st[i], cudaStreamNonBlocking);
        cudaEventCreateWithFlags(&eFork, cudaEventDisableTiming);
        cudaEventCreateWithFlags(&eCb, cudaEventDisableTiming);
        for (int i = 1; i < NCHAIN; i++)
            cudaEventCreateWithFlags(&eJoin[i], cudaEventDisableTiming);
    }

    // fork: side-chain preps run concurrently with chain-0 prep + cbfuse
    cudaEventRecord(eFork, 0);
    for (int i = 1; i < NCHAIN; i++) cudaStreamWaitEvent(st[i], eFork, 0);
    for (int i = 1; i < NCHAIN; i++)
        prep_kernel<<<NPART / 8, 256, 0, st[i]>>>(x, i * NPART);
    prep_kernel<<<NPART / 8, 256>>>(x, 0);
    cbfuse_kernel<<<(Q_ * K_) / 8, 256>>>(cbs);
    cudaEventRecord(eCb, 0);
    for (int i = 1; i < NCHAIN; i++) cudaStreamWaitEvent(st[i], eCb, 0);

    dim3 grid(NPART / BM, K_ / BN);
    for (int i = 0; i < NCHAIN; i++) {
        int rBase = i * NPART;
        for (int q = 0; q < Q_; q++) {
            const float* cb = cbs + (size_t)q * K_ * D_;
            gemm_dist_kernel<<<grid, 256, 0, st[i]>>>(q, rBase);
            fixup_update_kernel<<<NPART / 8, 256, 0, st[i]>>>(cb, x, xq, idx_out, q, rBase);
        }
    }

    for (int i = 1; i < NCHAIN; i++) {
        cudaEventRecord(eJoin[i], st[i]);
        cudaStreamWaitEvent(0, eJoin[i], 0);
    }
    finalize_kernel<<<1, 32>>>(loss_out);
}

// round 17
// speedup vs baseline: 1.4378x; 1.0026x over previous
#include <cuda_runtime.h>
#include <cstdint>

// Problem constants
#define N_ 32768
#define D_ 512
#define Q_ 4
#define K_ 2048
#define NCHAIN 4
#define NPART (N_ / NCHAIN)   // 8192

// GEMM tiling (int8)
#define BM 128
#define BN 128
#define BKI 64
#define NIT (D_ / BKI)   // 8
#define STAGES 3
#define CMAX 128
#define MARGIN 16.0f
#define TIE 0.125f

// ---------------- device scratch ----------------
__device__ float g_res[N_ * D_];                    // fp32 residual (64 MB)
__device__ int8_t g_qres[N_ * D_];                  // int8 residual (16 MB)
__device__ int8_t g_qcb[Q_ * K_ * D_];              // int8 codebooks (4 MB)
__device__ float g_rn2[N_];
__device__ float g_sa[N_];
__device__ float g_en2[Q_ * K_];
__device__ float g_sb[Q_ * K_];
__device__ unsigned long long g_key[N_];            // global coarse min (dist_bits<<32)|k
__device__ unsigned long long g_cand[(size_t)N_ * CMAX];
__device__ int g_ccnt[N_];
__device__ double g_lossp[256];

// ---------------- PTX helpers ----------------
__device__ __forceinline__ void cp_async16(uint32_t saddr, const void* gaddr) {
    asm volatile("cp.async.cg.shared.global [%0], [%1], 16;" :: "r"(saddr), "l"(gaddr));
}
#define CP_COMMIT() asm volatile("cp.async.commit_group;")
#define CP_WAIT1()  asm volatile("cp.async.wait_group 1;")

__device__ __forceinline__ void ldsm4(uint32_t& r0, uint32_t& r1, uint32_t& r2, uint32_t& r3,
                                      uint32_t addr) {
    asm volatile("ldmatrix.sync.aligned.m8n8.x4.shared.b16 {%0,%1,%2,%3}, [%4];"
                 : "=r"(r0), "=r"(r1), "=r"(r2), "=r"(r3) : "r"(addr));
}
__device__ __forceinline__ void mma_s8(int* c, const uint32_t* a, const uint32_t* b) {
    asm volatile(
        "mma.sync.aligned.m16n8k32.row.col.s32.s8.s8.s32 "
        "{%0,%1,%2,%3}, {%4,%5,%6,%7}, {%8,%9}, {%0,%1,%2,%3};"
        : "+r"(c[0]), "+r"(c[1]), "+r"(c[2]), "+r"(c[3])
        : "r"(a[0]), "r"(a[1]), "r"(a[2]), "r"(a[3]), "r"(b[0]), "r"(b[1]));
}

__device__ __forceinline__ int8_t q8(float v, float inv) {
    int t = __float2int_rn(v * inv);
    t = max(-127, min(127, t));
    return (int8_t)t;
}

// ---------------- prep (per row-partition): res = x, rn2, amax, int8 quant ------
__global__ void prep_kernel(const float* __restrict__ x, int rBase) {
    int w = rBase + ((blockIdx.x * blockDim.x + threadIdx.x) >> 5);
    int lane = threadIdx.x & 31;
    const float4* row = reinterpret_cast<const float4*>(x + (size_t)w * D_);
    float4* rrow = reinterpret_cast<float4*>(g_res + (size_t)w * D_);
    float4 v[4];
    float ss = 0.0f, am = 0.0f;
#pragma unroll
    for (int i = 0; i < 4; i++) {
        v[i] = row[lane + i * 32];
        rrow[lane + i * 32] = v[i];
        ss += v[i].x * v[i].x + v[i].y * v[i].y + v[i].z * v[i].z + v[i].w * v[i].w;
        am = fmaxf(am, fmaxf(fmaxf(fabsf(v[i].x), fabsf(v[i].y)),
                             fmaxf(fabsf(v[i].z), fabsf(v[i].w))));
    }
#pragma unroll
    for (int off = 16; off > 0; off >>= 1) {
        ss += __shfl_xor_sync(0xFFFFFFFFu, ss, off);
        am = fmaxf(am, __shfl_xor_sync(0xFFFFFFFFu, am, off));
    }
    float inv = (am > 0.0f) ? 127.0f / am : 0.0f;
    char4* orow = reinterpret_cast<char4*>(g_qres + (size_t)w * D_);
#pragma unroll
    for (int i = 0; i < 4; i++) {
        char4 c;
        c.x = q8(v[i].x, inv); c.y = q8(v[i].y, inv);
        c.z = q8(v[i].z, inv); c.w = q8(v[i].w, inv);
        orow[lane + i * 32] = c;
    }
    if (lane == 0) { g_rn2[w] = ss; g_sa[w] = am / 127.0f; }
}

// ---------------- codebook: en2 + amax + int8 quant + global resets ----------------
__global__ void cbfuse_kernel(const float* __restrict__ cbs) {
    int gidx = blockIdx.x * blockDim.x + threadIdx.x;
    if (gidx < N_) { g_ccnt[gidx] = 0; g_key[gidx] = ~0ull; }
    if (gidx < 256) g_lossp[gidx] = 0.0;
    int w = gidx >> 5;
    int lane = threadIdx.x & 31;
    if (w >= Q_ * K_) return;
    const float4* row = reinterpret_cast<const float4*>(cbs + (size_t)w * D_);
    float4 v[4];
    float ss = 0.0f, am = 0.0f;
#pragma unroll
    for (int i = 0; i < 4; i++) {
        v[i] = row[lane + i * 32];
        ss += v[i].x * v[i].x + v[i].y * v[i].y + v[i].z * v[i].z + v[i].w * v[i].w;
        am = fmaxf(am, fmaxf(fmaxf(fabsf(v[i].x), fabsf(v[i].y)),
                             fmaxf(fabsf(v[i].z), fabsf(v[i].w))));
    }
#pragma unroll
    for (int off = 16; off > 0; off >>= 1) {
        ss += __shfl_xor_sync(0xFFFFFFFFu, ss, off);
        am = fmaxf(am, __shfl_xor_sync(0xFFFFFFFFu, am, off));
    }
    float inv = (am > 0.0f) ? 127.0f / am : 0.0f;
    char4* orow = reinterpret_cast<char4*>(g_qcb + (size_t)w * D_);
#pragma unroll
    for (int i = 0; i < 4; i++) {
        char4 c;
        c.x = q8(v[i].x, inv); c.y = q8(v[i].y, inv);
        c.z = q8(v[i].z, inv); c.w = q8(v[i].w, inv);
        orow[lane + i * 32] = c;
    }
    if (lane == 0) { g_en2[w] = ss; g_sb[w] = am / 127.0f; }
}

// ---------------- int8 coarse GEMM + candidate selection (row partition) ----------
// 3-stage cp.async ring, prefetch issued AFTER the barrier (race-free; R5-R12 proven).
__global__ __launch_bounds__(256, 2)
void gemm_dist_kernel(int q, int rBase) {
    __shared__ alignas(128) int8_t sA[STAGES][BM * BKI];
    __shared__ alignas(128) int8_t sB[STAGES][BN * BKI];
    __shared__ float s_en2[BN];
    __shared__ float s_rn2[BM];
    __shared__ float s_sa[BM];
    __shared__ float s_sb[BN];
    __shared__ unsigned long long rowKey[BM];

    const int tid = threadIdx.x;
    const int wid = tid >> 5;
    const int lane = tid & 31;
    const int warp_m = wid >> 1;
    const int warp_n = wid & 1;
    const int gid = lane >> 2;
    const int tig = lane & 3;

    const int nBase = rBase + blockIdx.x * BM;
    const int kBase = blockIdx.y * BN;

    if (tid < 128) {
        s_en2[tid] = g_en2[q * K_ + kBase + tid];
        s_sb[tid]  = g_sb[q * K_ + kBase + tid];
        s_rn2[tid] = g_rn2[nBase + tid];
        s_sa[tid]  = g_sa[nBase + tid];
        rowKey[tid] = ~0ull;
    }

    const int8_t* gA = g_qres;
    const int8_t* gB = g_qcb + (size_t)q * K_ * D_;

    uint32_t saA[STAGES], saB[STAGES];
#pragma unroll
    for (int s = 0; s < STAGES; s++) {
        saA[s] = (uint32_t)__cvta_generic_to_shared(&sA[s][0]);
        saB[s] = (uint32_t)__cvta_generic_to_shared(&sB[s][0]);
    }

    int c[2][8][4];
#pragma unroll
    for (int i = 0; i < 2; i++)
#pragma unroll
        for (int j = 0; j < 8; j++)
#pragma unroll
            for (int v = 0; v < 4; v++) c[i][j][v] = 0;

    auto load_tiles = [&](int s, int it) {
#pragma unroll
        for (int u = 0; u < 2; u++) {
            int cidx = tid + 256 * u;
            int r = cidx >> 2, ch = cidx & 3;
            uint32_t off = (uint32_t)(r * 64 + ((ch ^ (r & 3)) << 4));
            cp_async16(saA[s] + off, gA + (size_t)(nBase + r) * D_ + it * BKI + ch * 16);
            cp_async16(saB[s] + off, gB + (size_t)(kBase + r) * D_ + it * BKI + ch * 16);
        }
    };

    load_tiles(0, 0); CP_COMMIT();
    load_tiles(1, 1); CP_COMMIT();

    for (int it = 0; it < NIT; it++) {
        int buf = it % STAGES;
        CP_WAIT1();
        __syncthreads();                 // all warps done with it-1's slot; group it ready
        if (it + 2 < NIT) load_tiles((it + 2) % STAGES, it + 2);
        CP_COMMIT();

#pragma unroll
        for (int kk = 0; kk < 2; kk++) {
            uint32_t a[2][4], b[8][2];
#pragma unroll
            for (int i = 0; i < 2; i++) {
                int row = warp_m * 32 + i * 16 + (lane & 7) + ((lane >> 3) & 1) * 8;
                int ch = kk * 2 + (lane >> 4);
                uint32_t addr = saA[buf] + (uint32_t)(row * 64 + ((ch ^ (row & 3)) << 4));
                ldsm4(a[i][0], a[i][1], a[i][2], a[i][3], addr);
            }
#pragma unroll
            for (int p = 0; p < 4; p++) {
                int row = warp_n * 64 + p * 16 + (lane & 7) + ((lane >> 4) & 1) * 8;
                int ch = kk * 2 + ((lane >> 3) & 1);
                uint32_t addr = saB[buf] + (uint32_t)(row * 64 + ((ch ^ (row & 3)) << 4));
                ldsm4(b[2 * p][0], b[2 * p][1], b[2 * p + 1][0], b[2 * p + 1][1], addr);
            }
#pragma unroll
            for (int i = 0; i < 2; i++)
#pragma unroll
                for (int j = 0; j < 8; j++)
                    mma_s8(c[i][j], a[i], b[j]);
        }
    }

    // ---- epilogue pass 1: dists + block-local row min ----
#pragma unroll
    for (int i = 0; i < 2; i++) {
#pragma unroll
        for (int r2 = 0; r2 < 2; r2++) {
            int rowL = warp_m * 32 + i * 16 + gid + r2 * 8;
            float rn2 = s_rn2[rowL];
            float sc2 = 2.0f * s_sa[rowL];
            unsigned long long best = ~0ull;
#pragma unroll
            for (int j = 0; j < 8; j++) {
                int colL = warp_n * 64 + j * 8 + tig * 2;
                float d0 = rn2 + s_en2[colL] - sc2 * s_sb[colL] * (float)c[i][j][r2 * 2 + 0];
                float d1 = rn2 + s_en2[colL + 1] - sc2 * s_sb[colL + 1] * (float)c[i][j][r2 * 2 + 1];
                c[i][j][r2 * 2 + 0] = __float_as_int(d0);
                c[i][j][r2 * 2 + 1] = __float_as_int(d1);
                unsigned kg0 = (unsigned)(kBase + colL);
                unsigned long long k0 = ((unsigned long long)__float_as_uint(d0) << 32) | kg0;
                unsigned long long k1 = ((unsigned long long)__float_as_uint(d1) << 32) | (kg0 + 1);
                if (k0 < best) best = k0;
                if (k1 < best) best = k1;
            }
#pragma unroll
            for (int m = 1; m < 4; m <<= 1) {
                unsigned long long o = __shfl_xor_sync(0xFFFFFFFFu, best, m);
                if (o < best) best = o;
            }
            if (tig == 0) atomicMin(&rowKey[rowL], best);
        }
    }
    __syncthreads();
    if (tid < 128) {
        unsigned long long mine = rowKey[tid];
        unsigned long long old = atomicMin(&g_key[nBase + tid], mine);
        rowKey[tid] = (old < mine) ? old : mine;
    }
    __syncthreads();

    // ---- epilogue pass 2: append candidates below (best-known min) + MARGIN ----
#pragma unroll
    for (int i = 0; i < 2; i++) {
#pragma unroll
        for (int r2 = 0; r2 < 2; r2++) {
            int rowL = warp_m * 32 + i * 16 + gid + r2 * 8;
            int rowG = nBase + rowL;
            float thr = __uint_as_float((unsigned)(rowKey[rowL] >> 32)) + MARGIN;
#pragma unroll
            for (int j = 0; j < 8; j++) {
                int colL = warp_n * 64 + j * 8 + tig * 2;
#pragma unroll
                for (int v = 0; v < 2; v++) {
                    float d = __int_as_float(c[i][j][r2 * 2 + v]);
                    if (d < thr) {
                        int p = atomicAdd(&g_ccnt[rowG], 1);
                        if (p < CMAX)
                            g_cand[(size_t)rowG * CMAX + p] =
                                ((unsigned long long)__float_as_uint(d) << 32) |
                                (unsigned)(kBase + colL + v);
                    }
                }
            }
        }
    }
}

// ---------------- fixup + full row update, warp-per-row (row partition) ------------
__global__ __launch_bounds__(256)
void fixup_update_kernel(const float* __restrict__ cb, const float* __restrict__ x,
                         float* __restrict__ xq, float* __restrict__ idx_out,
                         int q, int rBase) {
    __shared__ float s_dist[8][CMAX];
    __shared__ alignas(16) float sres[8][D_];

    const int tid = threadIdx.x;
    const int wid = tid >> 5;
    const int lane = tid & 31;
    const int r = rBase + blockIdx.x * 8 + wid;

    const float4* res4 = reinterpret_cast<const float4*>(g_res + (size_t)r * D_);
    float4 rv[4];
#pragma unroll
    for (int i = 0; i < 4; i++) rv[i] = res4[lane + i * 32];

    unsigned long long gk = g_key[r];
    int nc = min(g_ccnt[r], CMAX);
    float thr = __uint_as_float((unsigned)(gk >> 32)) + MARGIN;
    float rn2 = g_rn2[r];

    int kbest;
    if (nc <= 1) {
        kbest = (int)(unsigned)(gk & 0xFFFFFFFFull);
    } else {
        // pass A: warp-parallel fp32 approx distance per candidate
        float bestd = 3.4e38f;
        for (int ci = 0; ci < nc; ci++) {
            unsigned long long cd = g_cand[(size_t)r * CMAX + ci];
            float cdist = __uint_as_float((unsigned)(cd >> 32));
            if (cdist >= thr) { if (lane == 0) s_dist[wid][ci] = 3.4e38f; continue; }
            int k = (int)(unsigned)(cd & 0xFFFFFFFFull);
            const float4* crow = reinterpret_cast<const float4*>(cb + (size_t)k * D_);
            float dot = 0.0f;
#pragma unroll
            for (int i = 0; i < 4; i++) {
                float4 e = crow[lane + i * 32];
                dot += rv[i].x * e.x + rv[i].y * e.y + rv[i].z * e.z + rv[i].w * e.w;
            }
#pragma unroll
            for (int off = 16; off > 0; off >>= 1)
                dot += __shfl_xor_sync(0xFFFFFFFFu, dot, off);
            float da = rn2 + __ldg(&g_en2[q * K_ + k]) - 2.0f * dot;
            if (lane == 0) s_dist[wid][ci] = da;
            if (da < bestd) bestd = da;
        }
        __syncwarp();
        // pass B: tie set = candidates within TIE of approx best
        int tcnt = 0, tfirst = -1;
        for (int ci = lane; ci < nc; ci += 32) {
            if (s_dist[wid][ci] < bestd + TIE) { tcnt++; tfirst = ci; }
        }
#pragma unroll
        for (int off = 16; off > 0; off >>= 1) {
            tcnt += __shfl_xor_sync(0xFFFFFFFFu, tcnt, off);
            int o = __shfl_xor_sync(0xFFFFFFFFu, tfirst, off);
            if (o >= 0 && (tfirst < 0)) tfirst = o;
        }
        if (tcnt == 1) {
            unsigned long long cd = g_cand[(size_t)r * CMAX + tfirst];
            kbest = (int)(unsigned)(cd & 0xFFFFFFFFull);
        } else {
            // rare: exact ascending-d sequential fmaf chain (R1 bits) per tie
#pragma unroll
            for (int i = 0; i < 4; i++)
                reinterpret_cast<float4*>(sres[wid])[lane + i * 32] = rv[i];
            __syncwarp();
            unsigned long long best = ~0ull;
            for (int ci = 0; ci < nc; ci++) {
                if (s_dist[wid][ci] >= bestd + TIE) continue;
                unsigned long long cd = g_cand[(size_t)r * CMAX + ci];
                int k = (int)(unsigned)(cd & 0xFFFFFFFFull);
                if (lane == 0) {
                    const float* crow = cb + (size_t)k * D_;
                    float dot = 0.0f;
#pragma unroll 8
                    for (int d = 0; d < D_; d++)
                        dot = fmaf(sres[wid][d], __ldg(crow + d), dot);
                    float dist = (rn2 + g_en2[q * K_ + k]) - 2.0f * dot;
                    unsigned long long key =
                        ((unsigned long long)__float_as_uint(dist) << 32) | (unsigned)k;
                    if (key < best) best = key;
                }
            }
            best = __shfl_sync(0xFFFFFFFFu, best, 0);
            kbest = (int)(unsigned)(best & 0xFFFFFFFFull);
        }
    }

    // residual update + reductions
    const float4* e4 = reinterpret_cast<const float4*>(cb + (size_t)kbest * D_);
    float4 nr[4];
    float ss = 0.0f, am = 0.0f;
#pragma unroll
    for (int i = 0; i < 4; i++) {
        float4 e = e4[lane + i * 32];
        nr[i] = make_float4(rv[i].x - e.x, rv[i].y - e.y, rv[i].z - e.z, rv[i].w - e.w);
        ss += nr[i].x * nr[i].x + nr[i].y * nr[i].y + nr[i].z * nr[i].z + nr[i].w * nr[i].w;
        am = fmaxf(am, fmaxf(fmaxf(fabsf(nr[i].x), fabsf(nr[i].y)),
                             fmaxf(fabsf(nr[i].z), fabsf(nr[i].w))));
    }
#pragma unroll
    for (int off = 16; off > 0; off >>= 1) {
        ss += __shfl_xor_sync(0xFFFFFFFFu, ss, off);
        am = fmaxf(am, __shfl_xor_sync(0xFFFFFFFFu, am, off));
    }

    if (q < Q_ - 1) {
        float4* orow = reinterpret_cast<float4*>(g_res + (size_t)r * D_);
        float inv = (am > 0.0f) ? 127.0f / am : 0.0f;
        char4* qrow = reinterpret_cast<char4*>(g_qres + (size_t)r * D_);
#pragma unroll
        for (int i = 0; i < 4; i++) {
            orow[lane + i * 32] = nr[i];
            char4 c;
            c.x = q8(nr[i].x, inv); c.y = q8(nr[i].y, inv);
            c.z = q8(nr[i].z, inv); c.w = q8(nr[i].w, inv);
            qrow[lane + i * 32] = c;
        }
        if (lane == 0) {
            g_rn2[r] = ss;
            g_sa[r] = am / 127.0f;
            g_ccnt[r] = 0;
            g_key[r] = ~0ull;
        }
    } else {
        const float4* x4 = reinterpret_cast<const float4*>(x + (size_t)r * D_);
        float4* o4 = reinterpret_cast<float4*>(xq + (size_t)r * D_);
#pragma unroll
        for (int i = 0; i < 4; i++) {
            float4 xv = x4[lane + i * 32];
            o4[lane + i * 32] = make_float4(xv.x - nr[i].x, xv.y - nr[i].y,
                                            xv.z - nr[i].z, xv.w - nr[i].w);
        }
    }
    if (lane == 0) {
        idx_out[(size_t)r * Q_ + q] = (float)kbest;
        atomicAdd(&g_lossp[(q << 6) | (r & 63)], (double)ss);
    }
}

// ---------------- finalize mean loss ----------------
__global__ void finalize_kernel(float* __restrict__ loss_out) {
    if (threadIdx.x == 0) {
        double s = 0.0;
        for (int i = 0; i < 256; i++) s += g_lossp[i];
        double ml = (s * 1.25 / ((double)N_ * (double)D_)) / (double)Q_;
        *loss_out = (float)ml;
    }
}

// ---------------- launch: four independent row-quarter chains in the graph -------
// Stream topology identical to the R15 config that passed the teardown check:
// chain 0 on the legacy default stream; three created side streams.
extern "C" void kernel_launch(void* const* d_in, const int* in_sizes, int n_in,
                              void* d_out, int out_size) {
    const float* x = (const float*)d_in[0];
    const float* cbs = (const float*)d_in[1];
    float* out = (float*)d_out;
    float* xq = out;                                  // [N, D]
    float* loss_out = out + (size_t)N_ * D_;          // scalar
    float* idx_out = out + (size_t)N_ * D_ + 1;       // [N, Q] as float

    static cudaStream_t st[NCHAIN] = {nullptr, nullptr, nullptr, nullptr};
    static cudaEvent_t eFork = nullptr, eCb = nullptr;
    static cudaEvent_t eJoin[NCHAIN] = {nullptr, nullptr, nullptr, nullptr};
    if (st[1] == nullptr) {
        st[0] = 0;   // legacy default stream for chain 0
        for (int i = 1; i < NCHAIN; i++)
            cudaStreamCreateWithFlags(&st[i], cudaStreamNonBlocking);
        cudaEventCreateWithFlags(&eFork, cudaEventDisableTiming);
        cudaEventCreateWithFlags(&eCb, cudaEventDisableTiming);
        for (int i = 1; i < NCHAIN; i++)
            cudaEventCreateWithFlags(&eJoin[i], cudaEventDisableTiming);
    }

    // fork: side-chain preps run concurrently with chain-0 prep + cbfuse
    cudaEventRecord(eFork, 0);
    for (int i = 1; i < NCHAIN; i++) cudaStreamWaitEvent(st[i], eFork, 0);
    for (int i = 1; i < NCHAIN; i++)
        prep_kernel<<<NPART / 8, 256, 0, st[i]>>>(x, i * NPART);
    prep_kernel<<<NPART / 8, 256>>>(x, 0);
    cbfuse_kernel<<<(Q_ * K_) / 8, 256>>>(cbs);
    cudaEventRecord(eCb, 0);
    for (int i = 1; i < NCHAIN; i++) cudaStreamWaitEvent(st[i], eCb, 0);

    dim3 grid(NPART / BM, K_ / BN);
    for (int i = 0; i < NCHAIN; i++) {
        int rBase = i * NPART;
        for (int q = 0; q < Q_; q++) {
            const float* cb = cbs + (size_t)q * K_ * D_;
            gemm_dist_kernel<<<grid, 256, 0, st[i]>>>(q, rBase);
            fixup_update_kernel<<<NPART / 8, 256, 0, st[i]>>>(cb, x, xq, idx_out, q, rBase);
        }
    }

    for (int i = 1; i < NCHAIN; i++) {
        cudaEventRecord(eJoin[i], st[i]);
        cudaStreamWaitEvent(0, eJoin[i], 0);
    }
    finalize_kernel<<<1, 32>>>(loss_out);
}